// round 7
// baseline (speedup 1.0000x reference)
#include <cuda_runtime.h>
#include <math.h>

// ---------------- scratch (no allocations allowed) ----------------
__device__ __align__(16) float g_bufA[100 * 6400];
__device__ __align__(16) float g_bufB[100 * 4608];
__device__ __align__(16) float g_z[100 * 2048];      // packed QKV: [n][q512|k512|v1024]
__device__ __align__(16) float g_o[100 * 1024];      // attention out, concat heads
__device__ __align__(16) float g_t[100 * 2048];      // FFN hidden
__device__ __align__(16) float g_part[4 * 100 * 512];// split-K partials

// ---------------- conv1: reads patches straight from x ----------------
__global__ void conv1_kernel(const float* __restrict__ x, const float* __restrict__ w,
                             const float* __restrict__ b, float* __restrict__ out) {
    __shared__ float s_in[3 * 20 * 20];
    __shared__ float s_w[8 * 3 * 9];
    __shared__ float s_b[8];
    const int p = blockIdx.x;
    const int r0 = 20 * (p % 10);
    const int c0 = 20 * (p / 10);
    for (int idx = threadIdx.x; idx < 1200; idx += blockDim.x) {
        int c = idx / 400, rem = idx % 400, y = rem / 20, xx = rem % 20;
        s_in[idx] = x[c * 40000 + (r0 + y) * 200 + c0 + xx];
    }
    for (int idx = threadIdx.x; idx < 216; idx += blockDim.x) s_w[idx] = w[idx];
    if (threadIdx.x < 8) s_b[threadIdx.x] = b[threadIdx.x];
    __syncthreads();
    for (int idx = threadIdx.x; idx < 8 * 18 * 18; idx += blockDim.x) {
        int oc = idx / 324, rem = idx % 324, oy = rem / 18, ox = rem % 18;
        float acc = s_b[oc];
        const float* wp = s_w + oc * 27;
#pragma unroll
        for (int ci = 0; ci < 3; ci++)
#pragma unroll
            for (int ky = 0; ky < 3; ky++)
#pragma unroll
                for (int kx = 0; kx < 3; kx++)
                    acc += s_in[ci * 400 + (oy + ky) * 20 + ox + kx] * wp[ci * 9 + ky * 3 + kx];
        out[p * 2592 + idx] = acc;
    }
}

// ---------------- register-tiled conv: OCT oc x CHUNK spatial per thread ----------------
// Per-ci weight slice staged in smem; FMA:smem-load ratio = OCT*CHUNK/(OCT+CHUNK).
template <int CI, int CO, int SIN, int OCT, int CHUNK, bool RELU, int NT>
__global__ __launch_bounds__(NT) void conv_tile(const float* __restrict__ in,
                                                const float* __restrict__ w,
                                                const float* __restrict__ bias,
                                                float* __restrict__ out) {
    constexpr int KK = 9;
    constexpr int SOUT = SIN - 2;
    constexpr int SP = SOUT * SOUT;
    constexpr int SS = SIN * SIN;
    constexpr int NOC = CO / OCT;
    constexpr int NSP = SP / CHUNK;
    static_assert(NOC * NSP == NT, "thread count mismatch");
    __shared__ float s_in[CI * SS];
    __shared__ float s_w[CO * KK];
    const int p = blockIdx.x;
    const float* inp = in + (size_t)p * CI * SS;
    for (int i = threadIdx.x; i < CI * SS; i += NT) s_in[i] = inp[i];
    const int ocg = threadIdx.x / NSP;
    const int spg = threadIdx.x % NSP;
    const int oc0 = ocg * OCT, sp0 = spg * CHUNK;
    int off[CHUNK];
#pragma unroll
    for (int u = 0; u < CHUNK; u++) {
        int pos = sp0 + u;
        off[u] = (pos / SOUT) * SIN + (pos % SOUT);
    }
    float acc[OCT][CHUNK];
#pragma unroll
    for (int o = 0; o < OCT; o++)
#pragma unroll
        for (int u = 0; u < CHUNK; u++) acc[o][u] = 0.f;
    for (int ci = 0; ci < CI; ci++) {
        __syncthreads();
        for (int i = threadIdx.x; i < CO * KK; i += NT)
            s_w[i] = w[(i / KK) * (CI * KK) + ci * KK + (i % KK)];
        __syncthreads();
        const float* ib = s_in + ci * SS;
#pragma unroll
        for (int ky = 0; ky < 3; ky++)
#pragma unroll
            for (int kx = 0; kx < 3; kx++) {
                float wf[OCT];
#pragma unroll
                for (int o = 0; o < OCT; o++) wf[o] = s_w[(oc0 + o) * KK + ky * 3 + kx];
                float xf[CHUNK];
                const float* ip = ib + ky * SIN + kx;
#pragma unroll
                for (int u = 0; u < CHUNK; u++) xf[u] = ip[off[u]];
#pragma unroll
                for (int o = 0; o < OCT; o++)
#pragma unroll
                    for (int u = 0; u < CHUNK; u++) acc[o][u] += wf[o] * xf[u];
            }
    }
#pragma unroll
    for (int o = 0; o < OCT; o++) {
        float bv = bias[oc0 + o];
#pragma unroll
        for (int u = 0; u < CHUNK; u++) {
            float r = acc[o][u] + bv;
            if (RELU) r = fmaxf(r, 0.f);
            out[(size_t)p * CO * SP + (oc0 + o) * SP + sp0 + u] = r;
        }
    }
}

// ---------------- skinny GEMM core: 64x32 tile, 128 threads, 4x4/thread ----------------
#define GEMM_CORE(A_, lda_, BLOAD, KSTART, KLEN)                                        \
    __shared__ __align__(16) float As[16][64];                                          \
    __shared__ __align__(16) float Bs[16][32];                                          \
    const int t = threadIdx.x;                                                          \
    const int ty = t >> 3, tx = t & 7;                                                  \
    const int am = t >> 2, ak4 = (t & 3) << 2;                                          \
    const int bk = t >> 3, bn4 = (t & 7) << 2;                                          \
    float acc[4][4] = {};                                                               \
    for (int kk0 = (KSTART); kk0 < (KSTART) + (KLEN); kk0 += 16) {                      \
        float4 a0 = make_float4(0.f, 0.f, 0.f, 0.f), a1 = a0;                           \
        if (m0 + am < M) a0 = *(const float4*)((A_) + (long long)(m0 + am) * (lda_) + kk0 + ak4); \
        if (m0 + am + 32 < M)                                                           \
            a1 = *(const float4*)((A_) + (long long)(m0 + am + 32) * (lda_) + kk0 + ak4);\
        As[ak4 + 0][am] = a0.x; As[ak4 + 1][am] = a0.y;                                 \
        As[ak4 + 2][am] = a0.z; As[ak4 + 3][am] = a0.w;                                 \
        As[ak4 + 0][am + 32] = a1.x; As[ak4 + 1][am + 32] = a1.y;                       \
        As[ak4 + 2][am + 32] = a1.z; As[ak4 + 3][am + 32] = a1.w;                       \
        BLOAD;                                                                          \
        __syncthreads();                                                                \
        _Pragma("unroll")                                                               \
        for (int kk = 0; kk < 16; kk++) {                                               \
            float4 a4 = *(const float4*)(&As[kk][ty << 2]);                             \
            float4 b4 = *(const float4*)(&Bs[kk][tx << 2]);                             \
            acc[0][0] += a4.x * b4.x; acc[0][1] += a4.x * b4.y;                         \
            acc[0][2] += a4.x * b4.z; acc[0][3] += a4.x * b4.w;                         \
            acc[1][0] += a4.y * b4.x; acc[1][1] += a4.y * b4.y;                         \
            acc[1][2] += a4.y * b4.z; acc[1][3] += a4.y * b4.w;                         \
            acc[2][0] += a4.z * b4.x; acc[2][1] += a4.z * b4.y;                         \
            acc[2][2] += a4.z * b4.z; acc[2][3] += a4.z * b4.w;                         \
            acc[3][0] += a4.w * b4.x; acc[3][1] += a4.w * b4.y;                         \
            acc[3][2] += a4.w * b4.z; acc[3][3] += a4.w * b4.w;                         \
        }                                                                               \
        __syncthreads();                                                                \
    }

// generic: C = A@B with optional bias/relu/resid, or plain store (split-K partial)
template <bool RELU, bool BIAS, bool RESID, bool PLAIN>
__global__ __launch_bounds__(128) void gemmS(const float* __restrict__ A,
                                             const float* __restrict__ B,
                                             const float* __restrict__ bias,
                                             float* __restrict__ C, int M, int N, int K,
                                             int lda, int ldb, int ldc, int kPerZ,
                                             long long strideCz) {
    const int m0 = blockIdx.y * 64, n0 = blockIdx.x * 32;
    const int z = blockIdx.z;
    C += (long long)z * strideCz;
    GEMM_CORE(A, lda,
              { *(float4*)(&Bs[bk][bn4]) =
                    *(const float4*)(B + (long long)(kk0 + bk) * ldb + n0 + bn4); },
              z * kPerZ, kPerZ)
#pragma unroll
    for (int i = 0; i < 4; i++) {
        int m = m0 + (ty << 2) + i;
        if (m >= M) break;
#pragma unroll
        for (int j = 0; j < 4; j++) {
            int n = n0 + (tx << 2) + j;
            float v = acc[i][j];
            if (!PLAIN) {
                if (BIAS) v += bias[n];
                if (RELU) v = fmaxf(v, 0.f);
                if (RESID) v += C[(long long)m * ldc + n];
            }
            C[(long long)m * ldc + n] = v;
        }
    }
}

// fused QKV: Z[100,2048] = h @ [Wq|Wk|Wv], head-major columns
__global__ __launch_bounds__(128) void qkv_gemm(const float* __restrict__ A,
                                                const float* __restrict__ Wq,
                                                const float* __restrict__ Wk,
                                                const float* __restrict__ Wv,
                                                float* __restrict__ Z) {
    const int M = 100;
    const int m0 = blockIdx.y * 64, n0 = blockIdx.x * 32;
    const float* Bp;
    int ldb;
    if (n0 < 512) { Bp = Wq + (n0 >> 7) * (512 * 128) + (n0 & 127); ldb = 128; }
    else if (n0 < 1024) { int c = n0 - 512; Bp = Wk + (c >> 7) * (512 * 128) + (c & 127); ldb = 128; }
    else { int c = n0 - 1024; Bp = Wv + (c >> 8) * (512 * 256) + (c & 255); ldb = 256; }
    GEMM_CORE(A, 512,
              { *(float4*)(&Bs[bk][bn4]) =
                    *(const float4*)(Bp + (long long)(kk0 + bk) * ldb + bn4); },
              0, 512)
#pragma unroll
    for (int i = 0; i < 4; i++) {
        int m = m0 + (ty << 2) + i;
        if (m >= M) break;
#pragma unroll
        for (int j = 0; j < 4; j++)
            Z[(long long)m * 2048 + n0 + (tx << 2) + j] = acc[i][j];
    }
}

// conv10 as GEMM with transposed B (W[512][1024]) + bias + location embedding -> h
__global__ __launch_bounds__(128) void gemmT_loc(const float* __restrict__ A,
                                                 const float* __restrict__ W,
                                                 const float* __restrict__ bias,
                                                 float* __restrict__ C) {
    const int M = 100;
    const int m0 = blockIdx.y * 64, n0 = blockIdx.x * 32;
    const int bn = threadIdx.x & 31, k4 = ((threadIdx.x >> 5) & 3) << 2;
    GEMM_CORE(A, 1024,
              {
                  float4 wv = *(const float4*)(W + (long long)(n0 + bn) * 1024 + kk0 + k4);
                  Bs[k4 + 0][bn] = wv.x; Bs[k4 + 1][bn] = wv.y;
                  Bs[k4 + 2][bn] = wv.z; Bs[k4 + 3][bn] = wv.w;
              },
              0, 1024)
#pragma unroll
    for (int i = 0; i < 4; i++) {
        int m = m0 + (ty << 2) + i;
        if (m >= M) break;
        float pos = 20.f * (float)(m / 10);
#pragma unroll
        for (int j = 0; j < 4; j++) {
            int n = n0 + (tx << 2) + j;
            float v = acc[i][j] + bias[n];
            int kkn = (n < 256) ? n : n - 256;
            float inv = exp2f(-(2.f * (float)kkn / 256.f) * 13.287712379549449f);
            float ang = pos * inv;
            v += (n < 256) ? sinf(ang) : cosf(ang);
            C[(long long)m * 512 + n] = v;
        }
    }
}

// ---------------- fused attention (reads packed Z) ----------------
__global__ void attn_kernel(const float* __restrict__ Z, float* __restrict__ O) {
    const int n = blockIdx.x, h = blockIdx.y;
    __shared__ float sq[128];
    __shared__ float sa[100];
    __shared__ float red[8];
    const int tid = threadIdx.x;
    if (tid < 128) sq[tid] = Z[n * 2048 + h * 128 + tid];
    __syncthreads();
    float s = -1e30f;
    if (tid < 100) {
        const float* kr = Z + tid * 2048 + 512 + h * 128;
        float acc = 0.f;
#pragma unroll 8
        for (int i = 0; i < 128; i++) acc += sq[i] * kr[i];
        s = acc * 0.1f;
    }
    float v = s;
#pragma unroll
    for (int o = 16; o; o >>= 1) v = fmaxf(v, __shfl_xor_sync(0xffffffffu, v, o));
    if ((tid & 31) == 0) red[tid >> 5] = v;
    __syncthreads();
    float mx = red[0];
#pragma unroll
    for (int i = 1; i < 8; i++) mx = fmaxf(mx, red[i]);
    float e = (tid < 100) ? expf(s - mx) : 0.f;
    float sv = e;
#pragma unroll
    for (int o = 16; o; o >>= 1) sv += __shfl_xor_sync(0xffffffffu, sv, o);
    __syncthreads();
    if ((tid & 31) == 0) red[tid >> 5] = sv;
    __syncthreads();
    float sum = 0.f;
#pragma unroll
    for (int i = 0; i < 8; i++) sum += red[i];
    if (tid < 100) sa[tid] = e / sum;
    __syncthreads();
    const float* vb = Z + 1024 + h * 256;
    float acc = 0.f;
#pragma unroll 4
    for (int m = 0; m < 100; m++) acc += sa[m] * vb[m * 2048 + tid];
    O[n * 1024 + h * 256 + tid] = acc;
}

// ---------------- split-K reduce: h += sum(parts) (+bias) ----------------
template <bool HASB>
__global__ void redAdd(float* __restrict__ h, const float* __restrict__ part,
                       const float* __restrict__ bias) {
    int i = blockIdx.x * blockDim.x + threadIdx.x;
    if (i < 51200) {
        float s = part[i] + part[i + 51200] + part[i + 102400] + part[i + 153600];
        if (HASB) s += bias[i & 511];
        h[i] += s;
    }
}

// ---------------- host launcher ----------------
extern "C" void kernel_launch(void* const* d_in, const int* in_sizes, int n_in,
                              void* d_out, int out_size) {
    const float* x = (const float*)d_in[0];
    const float* cw[10];
    const float* cb[10];
    for (int i = 0; i < 10; i++) {
        cw[i] = (const float*)d_in[1 + 2 * i];
        cb[i] = (const float*)d_in[2 + 2 * i];
    }
    const float* Wq = (const float*)d_in[21];
    const float* Wk = (const float*)d_in[22];
    const float* Wv = (const float*)d_in[23];
    const float* Wo = (const float*)d_in[24];
    const float* W1 = (const float*)d_in[25];
    const float* b1 = (const float*)d_in[26];
    const float* W2 = (const float*)d_in[27];
    const float* b2 = (const float*)d_in[28];
    float* h = (float*)d_out;

    float *bufA, *bufB, *z, *o, *t, *part;
    cudaGetSymbolAddress((void**)&bufA, g_bufA);
    cudaGetSymbolAddress((void**)&bufB, g_bufB);
    cudaGetSymbolAddress((void**)&z, g_z);
    cudaGetSymbolAddress((void**)&o, g_o);
    cudaGetSymbolAddress((void**)&t, g_t);
    cudaGetSymbolAddress((void**)&part, g_part);

    // ---- conv stack ----
    conv1_kernel<<<100, 256>>>(x, cw[0], cb[0], bufA);                       // 3->8, 18
    conv_tile<8, 16, 18, 2, 8, true, 256><<<100, 256>>>(bufA, cw[1], cb[1], bufB);   // 16
    conv_tile<16, 32, 16, 4, 7, false, 224><<<100, 224>>>(bufB, cw[2], cb[2], bufA); // 14
    conv_tile<32, 32, 14, 4, 6, true, 192><<<100, 192>>>(bufA, cw[3], cb[3], bufB);  // 12
    conv_tile<32, 64, 12, 4, 10, true, 160><<<100, 160>>>(bufB, cw[4], cb[4], bufA); // 10
    conv_tile<64, 64, 10, 4, 8, true, 128><<<100, 128>>>(bufA, cw[5], cb[5], bufB);  // 8
    conv_tile<64, 128, 8, 4, 9, true, 128><<<100, 128>>>(bufB, cw[6], cb[6], bufA);  // 6
    conv_tile<128, 128, 6, 4, 4, true, 128><<<100, 128>>>(bufA, cw[7], cb[7], bufB); // 4
    conv_tile<128, 256, 4, 4, 2, true, 128><<<100, 128>>>(bufB, cw[8], cb[8], bufA); // 2
    gemmT_loc<<<dim3(16, 2), 128>>>(bufA, cw[9], cb[9], h);  // 1x1 conv + loc emb

    // ---- 12 encoder layers ----
    for (int l = 0; l < 12; l++) {
        const float* wq = Wq + (size_t)l * 4 * 512 * 128;
        const float* wk = Wk + (size_t)l * 4 * 512 * 128;
        const float* wv = Wv + (size_t)l * 4 * 512 * 256;
        const float* wo = Wo + (size_t)l * 1024 * 512;
        const float* w1 = W1 + (size_t)l * 512 * 2048;
        const float* bb1 = b1 + (size_t)l * 2048;
        const float* w2 = W2 + (size_t)l * 2048 * 512;
        const float* bb2 = b2 + (size_t)l * 512;

        qkv_gemm<<<dim3(64, 2), 128>>>(h, wq, wk, wv, z);
        attn_kernel<<<dim3(100, 4), 256>>>(z, o);
        // h += O @ Wo   (split-K=4 -> partials -> reduce)
        gemmS<false, false, false, true><<<dim3(16, 2, 4), 128>>>(
            o, wo, nullptr, part, 100, 512, 1024, 1024, 512, 512, 256, 51200LL);
        redAdd<false><<<200, 256>>>(h, part, nullptr);
        // t = relu(h @ W1 + b1)
        gemmS<true, true, false, false><<<dim3(64, 2, 1), 128>>>(
            h, w1, bb1, t, 100, 2048, 512, 512, 2048, 2048, 512, 0LL);
        // h += t @ W2 + b2   (split-K=4)
        gemmS<false, false, false, true><<<dim3(16, 2, 4), 128>>>(
            t, w2, nullptr, part, 100, 512, 2048, 2048, 512, 512, 512, 51200LL);
        redAdd<true><<<200, 256>>>(h, part, bb2);
    }
}

// round 8
// speedup vs baseline: 1.4126x; 1.4126x over previous
#include <cuda_runtime.h>
#include <math.h>

// ---------------- scratch ----------------
__device__ __align__(16) float g_bufA[100 * 6400];
__device__ __align__(16) float g_bufB[100 * 4608];
__device__ __align__(16) float g_z[100 * 2048];
__device__ __align__(16) float g_zp[2 * 100 * 2048];
__device__ __align__(16) float g_o[100 * 1024];
__device__ __align__(16) float g_t[100 * 2048];
__device__ __align__(16) float g_tp[2 * 100 * 2048];
__device__ __align__(16) float g_part[8 * 100 * 512];

__device__ __forceinline__ float4 ld4(const float* p) { return *(const float4*)p; }

// ---------------- conv1 ----------------
__global__ void conv1_kernel(const float* __restrict__ x, const float* __restrict__ w,
                             const float* __restrict__ b, float* __restrict__ out) {
    __shared__ float s_in[1200];
    __shared__ float s_w[216];
    __shared__ float s_b[8];
    const int p = blockIdx.x;
    const int r0 = 20 * (p % 10), c0 = 20 * (p / 10);
    for (int idx = threadIdx.x; idx < 1200; idx += blockDim.x) {
        int c = idx / 400, rem = idx % 400, y = rem / 20, xx = rem % 20;
        s_in[idx] = x[c * 40000 + (r0 + y) * 200 + c0 + xx];
    }
    for (int idx = threadIdx.x; idx < 216; idx += blockDim.x) s_w[idx] = w[idx];
    if (threadIdx.x < 8) s_b[threadIdx.x] = b[threadIdx.x];
    __syncthreads();
    for (int idx = threadIdx.x; idx < 8 * 324; idx += blockDim.x) {
        int oc = idx / 324, rem = idx % 324, oy = rem / 18, ox = rem % 18;
        float acc = s_b[oc];
        const float* wp = s_w + oc * 27;
#pragma unroll
        for (int ci = 0; ci < 3; ci++)
#pragma unroll
            for (int ky = 0; ky < 3; ky++)
#pragma unroll
                for (int kx = 0; kx < 3; kx++)
                    acc += s_in[ci * 400 + (oy + ky) * 20 + ox + kx] * wp[ci * 9 + ky * 3 + kx];
        out[p * 2592 + idx] = acc;
    }
}

// ---------------- register-tiled conv (unchanged) ----------------
template <int CI, int CO, int SIN, int OCT, int CHUNK, bool RELU, int NT>
__global__ __launch_bounds__(NT) void conv_tile(const float* __restrict__ in,
                                                const float* __restrict__ w,
                                                const float* __restrict__ bias,
                                                float* __restrict__ out) {
    constexpr int KK = 9;
    constexpr int SOUT = SIN - 2;
    constexpr int SP = SOUT * SOUT;
    constexpr int SS = SIN * SIN;
    constexpr int NSP = SP / CHUNK;
    __shared__ float s_in[CI * SS];
    __shared__ float s_w[CO * KK];
    const int p = blockIdx.x;
    const float* inp = in + (size_t)p * CI * SS;
    for (int i = threadIdx.x; i < CI * SS; i += NT) s_in[i] = inp[i];
    const int ocg = threadIdx.x / NSP;
    const int spg = threadIdx.x % NSP;
    const int oc0 = ocg * OCT, sp0 = spg * CHUNK;
    int off[CHUNK];
#pragma unroll
    for (int u = 0; u < CHUNK; u++) {
        int pos = sp0 + u;
        off[u] = (pos / SOUT) * SIN + (pos % SOUT);
    }
    float acc[OCT][CHUNK] = {};
    for (int ci = 0; ci < CI; ci++) {
        __syncthreads();
        for (int i = threadIdx.x; i < CO * KK; i += NT)
            s_w[i] = w[(i / KK) * (CI * KK) + ci * KK + (i % KK)];
        __syncthreads();
        const float* ib = s_in + ci * SS;
#pragma unroll
        for (int ky = 0; ky < 3; ky++)
#pragma unroll
            for (int kx = 0; kx < 3; kx++) {
                float wf[OCT];
#pragma unroll
                for (int o = 0; o < OCT; o++) wf[o] = s_w[(oc0 + o) * KK + ky * 3 + kx];
                float xf[CHUNK];
                const float* ip = ib + ky * SIN + kx;
#pragma unroll
                for (int u = 0; u < CHUNK; u++) xf[u] = ip[off[u]];
#pragma unroll
                for (int o = 0; o < OCT; o++)
#pragma unroll
                    for (int u = 0; u < CHUNK; u++) acc[o][u] += wf[o] * xf[u];
            }
    }
#pragma unroll
    for (int o = 0; o < OCT; o++) {
        float bv = bias[oc0 + o];
#pragma unroll
        for (int u = 0; u < CHUNK; u++) {
            float r = acc[o][u] + bv;
            if (RELU) r = fmaxf(r, 0.f);
            out[(size_t)p * CO * SP + (oc0 + o) * SP + sp0 + u] = r;
        }
    }
}

// ---------------- gemmT_loc (conv10 + location embedding, unchanged) ----------------
__global__ __launch_bounds__(128) void gemmT_loc(const float* __restrict__ A,
                                                 const float* __restrict__ W,
                                                 const float* __restrict__ bias,
                                                 float* __restrict__ C) {
    const int M = 100;
    __shared__ __align__(16) float As[16][64];
    __shared__ __align__(16) float Bs[16][32];
    const int t = threadIdx.x;
    const int ty = t >> 3, tx = t & 7;
    const int am = t >> 2, ak4 = (t & 3) << 2;
    const int bn = t & 31, k4 = ((t >> 5) & 3) << 2;
    const int m0 = blockIdx.y * 64, n0 = blockIdx.x * 32;
    float acc[4][4] = {};
    for (int kk0 = 0; kk0 < 1024; kk0 += 16) {
        float4 a0 = make_float4(0.f, 0.f, 0.f, 0.f), a1 = a0;
        if (m0 + am < M) a0 = ld4(A + (long long)(m0 + am) * 1024 + kk0 + ak4);
        if (m0 + am + 32 < M) a1 = ld4(A + (long long)(m0 + am + 32) * 1024 + kk0 + ak4);
        As[ak4 + 0][am] = a0.x; As[ak4 + 1][am] = a0.y;
        As[ak4 + 2][am] = a0.z; As[ak4 + 3][am] = a0.w;
        As[ak4 + 0][am + 32] = a1.x; As[ak4 + 1][am + 32] = a1.y;
        As[ak4 + 2][am + 32] = a1.z; As[ak4 + 3][am + 32] = a1.w;
        float4 wv = ld4(W + (long long)(n0 + bn) * 1024 + kk0 + k4);
        Bs[k4 + 0][bn] = wv.x; Bs[k4 + 1][bn] = wv.y;
        Bs[k4 + 2][bn] = wv.z; Bs[k4 + 3][bn] = wv.w;
        __syncthreads();
#pragma unroll
        for (int kk = 0; kk < 16; kk++) {
            float4 a4 = *(const float4*)(&As[kk][ty << 2]);
            float4 b4 = *(const float4*)(&Bs[kk][tx << 2]);
            acc[0][0] += a4.x * b4.x; acc[0][1] += a4.x * b4.y; acc[0][2] += a4.x * b4.z; acc[0][3] += a4.x * b4.w;
            acc[1][0] += a4.y * b4.x; acc[1][1] += a4.y * b4.y; acc[1][2] += a4.y * b4.z; acc[1][3] += a4.y * b4.w;
            acc[2][0] += a4.z * b4.x; acc[2][1] += a4.z * b4.y; acc[2][2] += a4.z * b4.z; acc[2][3] += a4.z * b4.w;
            acc[3][0] += a4.w * b4.x; acc[3][1] += a4.w * b4.y; acc[3][2] += a4.w * b4.z; acc[3][3] += a4.w * b4.w;
        }
        __syncthreads();
    }
#pragma unroll
    for (int i = 0; i < 4; i++) {
        int m = m0 + (ty << 2) + i;
        if (m >= M) break;
        float pos = 20.f * (float)(m / 10);
#pragma unroll
        for (int j = 0; j < 4; j++) {
            int n = n0 + (tx << 2) + j;
            float v = acc[i][j] + bias[n];
            int kkn = (n < 256) ? n : n - 256;
            float inv = exp2f(-(2.f * (float)kkn / 256.f) * 13.287712379549449f);
            float ang = pos * inv;
            v += (n < 256) ? sinf(ang) : cosf(ang);
            C[(long long)m * 512 + n] = v;
        }
    }
}

// ---------------- double-buffered GEMM core: BK=32, 64x32 tile, 128 threads ----------------
__device__ __forceinline__ void gemm_db(const float* A0, const float* A1, bool v0, bool v1,
                                        const float* Bb, int ldb, int k0, int nIter,
                                        float (*As)[32][64], float (*Bs)[32][32],
                                        float (&acc)[4][4]) {
    const int t = threadIdx.x;
    const int am = t >> 2, ac = (t & 3) << 3;
    const int bk = t >> 2, bc = (t & 3) << 3;
    const int ty = t >> 3, tx = t & 7;
    (void)bk;
    const float4 z4 = make_float4(0.f, 0.f, 0.f, 0.f);
    {
        float4 a0 = v0 ? ld4(A0 + k0) : z4, a1 = v0 ? ld4(A0 + k0 + 4) : z4;
        float4 a2 = v1 ? ld4(A1 + k0) : z4, a3 = v1 ? ld4(A1 + k0 + 4) : z4;
        As[0][ac + 0][am] = a0.x; As[0][ac + 1][am] = a0.y;
        As[0][ac + 2][am] = a0.z; As[0][ac + 3][am] = a0.w;
        As[0][ac + 4][am] = a1.x; As[0][ac + 5][am] = a1.y;
        As[0][ac + 6][am] = a1.z; As[0][ac + 7][am] = a1.w;
        As[0][ac + 0][am + 32] = a2.x; As[0][ac + 1][am + 32] = a2.y;
        As[0][ac + 2][am + 32] = a2.z; As[0][ac + 3][am + 32] = a2.w;
        As[0][ac + 4][am + 32] = a3.x; As[0][ac + 5][am + 32] = a3.y;
        As[0][ac + 6][am + 32] = a3.z; As[0][ac + 7][am + 32] = a3.w;
        *(float4*)&Bs[0][t >> 2][bc] = ld4(Bb + (long long)k0 * ldb);
        *(float4*)&Bs[0][t >> 2][bc + 4] = ld4(Bb + (long long)k0 * ldb + 4);
    }
    __syncthreads();
    int buf = 0;
    for (int it = 0; it < nIter; ++it) {
        float4 a0, a1, a2, a3, b0, b1;
        const bool pf = (it + 1) < nIter;
        if (pf) {
            const int kn = k0 + ((it + 1) << 5);
            a0 = v0 ? ld4(A0 + kn) : z4; a1 = v0 ? ld4(A0 + kn + 4) : z4;
            a2 = v1 ? ld4(A1 + kn) : z4; a3 = v1 ? ld4(A1 + kn + 4) : z4;
            b0 = ld4(Bb + (long long)kn * ldb);
            b1 = ld4(Bb + (long long)kn * ldb + 4);
        }
#pragma unroll
        for (int kk = 0; kk < 32; kk++) {
            float4 a4 = *(const float4*)&As[buf][kk][ty << 2];
            float4 b4 = *(const float4*)&Bs[buf][kk][tx << 2];
            acc[0][0] += a4.x * b4.x; acc[0][1] += a4.x * b4.y; acc[0][2] += a4.x * b4.z; acc[0][3] += a4.x * b4.w;
            acc[1][0] += a4.y * b4.x; acc[1][1] += a4.y * b4.y; acc[1][2] += a4.y * b4.z; acc[1][3] += a4.y * b4.w;
            acc[2][0] += a4.z * b4.x; acc[2][1] += a4.z * b4.y; acc[2][2] += a4.z * b4.z; acc[2][3] += a4.z * b4.w;
            acc[3][0] += a4.w * b4.x; acc[3][1] += a4.w * b4.y; acc[3][2] += a4.w * b4.z; acc[3][3] += a4.w * b4.w;
        }
        if (pf) {
            const int nb = buf ^ 1;
            As[nb][ac + 0][am] = a0.x; As[nb][ac + 1][am] = a0.y;
            As[nb][ac + 2][am] = a0.z; As[nb][ac + 3][am] = a0.w;
            As[nb][ac + 4][am] = a1.x; As[nb][ac + 5][am] = a1.y;
            As[nb][ac + 6][am] = a1.z; As[nb][ac + 7][am] = a1.w;
            As[nb][ac + 0][am + 32] = a2.x; As[nb][ac + 1][am + 32] = a2.y;
            As[nb][ac + 2][am + 32] = a2.z; As[nb][ac + 3][am + 32] = a2.w;
            As[nb][ac + 4][am + 32] = a3.x; As[nb][ac + 5][am + 32] = a3.y;
            As[nb][ac + 6][am + 32] = a3.z; As[nb][ac + 7][am + 32] = a3.w;
            *(float4*)&Bs[nb][t >> 2][bc] = b0;
            *(float4*)&Bs[nb][t >> 2][bc + 4] = b1;
            __syncthreads();
            buf = nb;
        }
    }
}

// plain split-K partial: C[z] = A[:, zK..] @ B[zK.., n0..]
__global__ __launch_bounds__(128) void gemmP(const float* __restrict__ A,
                                             const float* __restrict__ B,
                                             float* __restrict__ C, int M, int lda,
                                             int ldb, int ldc, int kPerZ, long long sCz) {
    __shared__ __align__(16) float As[2][32][64];
    __shared__ __align__(16) float Bs[2][32][32];
    const int m0 = blockIdx.y * 64, n0 = blockIdx.x * 32;
    const int k0 = blockIdx.z * kPerZ;
    C += (long long)blockIdx.z * sCz;
    const int t = threadIdx.x;
    const int am = t >> 2, ac = (t & 3) << 3;
    const int bc = (t & 3) << 3;
    const int ty = t >> 3, tx = t & 7;
    const bool v0 = (m0 + am) < M, v1 = (m0 + am + 32) < M;
    const float* A0 = A + (long long)(m0 + am) * lda + ac;
    const float* A1 = A + (long long)(m0 + am + 32) * lda + ac;
    const float* Bb = B + (long long)(t >> 2) * ldb + n0 + bc;
    float acc[4][4] = {};
    gemm_db(A0, A1, v0, v1, Bb, ldb, k0, kPerZ >> 5, As, Bs, acc);
#pragma unroll
    for (int i = 0; i < 4; i++) {
        int m = m0 + (ty << 2) + i;
        if (m >= M) break;
#pragma unroll
        for (int j = 0; j < 4; j++)
            C[(long long)m * ldc + n0 + (tx << 2) + j] = acc[i][j];
    }
}

// qkv split-K partial: picks Wq/Wk/Wv by n0; writes zp[z][100][2048]
__global__ __launch_bounds__(128) void qkvP(const float* __restrict__ A,
                                            const float* __restrict__ Wq,
                                            const float* __restrict__ Wk,
                                            const float* __restrict__ Wv,
                                            float* __restrict__ C, int kPerZ) {
    __shared__ __align__(16) float As[2][32][64];
    __shared__ __align__(16) float Bs[2][32][32];
    const int M = 100;
    const int m0 = blockIdx.y * 64, n0 = blockIdx.x * 32;
    const int k0 = blockIdx.z * kPerZ;
    C += (long long)blockIdx.z * 204800;
    const float* Bp; int ldb;
    if (n0 < 512)       { Bp = Wq + (n0 >> 7) * 65536 + (n0 & 127); ldb = 128; }
    else if (n0 < 1024) { int c = n0 - 512;  Bp = Wk + (c >> 7) * 65536 + (c & 127); ldb = 128; }
    else                { int c = n0 - 1024; Bp = Wv + (c >> 8) * 131072 + (c & 255); ldb = 256; }
    const int t = threadIdx.x;
    const int am = t >> 2, ac = (t & 3) << 3;
    const int bc = (t & 3) << 3;
    const int ty = t >> 3, tx = t & 7;
    const bool v0 = (m0 + am) < M, v1 = (m0 + am + 32) < M;
    const float* A0 = A + (long long)(m0 + am) * 512 + ac;
    const float* A1 = A + (long long)(m0 + am + 32) * 512 + ac;
    const float* Bb = Bp + (long long)(t >> 2) * ldb + bc;
    float acc[4][4] = {};
    gemm_db(A0, A1, v0, v1, Bb, ldb, k0, kPerZ >> 5, As, Bs, acc);
#pragma unroll
    for (int i = 0; i < 4; i++) {
        int m = m0 + (ty << 2) + i;
        if (m >= M) break;
#pragma unroll
        for (int j = 0; j < 4; j++)
            C[(long long)m * 2048 + n0 + (tx << 2) + j] = acc[i][j];
    }
}

// ---------------- attention (reads packed Z, unchanged) ----------------
__global__ void attn_kernel(const float* __restrict__ Z, float* __restrict__ O) {
    const int n = blockIdx.x, h = blockIdx.y;
    __shared__ float sq[128];
    __shared__ float sa[100];
    __shared__ float red[8];
    const int tid = threadIdx.x;
    if (tid < 128) sq[tid] = Z[n * 2048 + h * 128 + tid];
    __syncthreads();
    float s = -1e30f;
    if (tid < 100) {
        const float* kr = Z + tid * 2048 + 512 + h * 128;
        float acc = 0.f;
#pragma unroll 8
        for (int i = 0; i < 128; i++) acc += sq[i] * kr[i];
        s = acc * 0.1f;
    }
    float v = s;
#pragma unroll
    for (int o = 16; o; o >>= 1) v = fmaxf(v, __shfl_xor_sync(0xffffffffu, v, o));
    if ((tid & 31) == 0) red[tid >> 5] = v;
    __syncthreads();
    float mx = red[0];
#pragma unroll
    for (int i = 1; i < 8; i++) mx = fmaxf(mx, red[i]);
    float e = (tid < 100) ? expf(s - mx) : 0.f;
    float sv = e;
#pragma unroll
    for (int o = 16; o; o >>= 1) sv += __shfl_xor_sync(0xffffffffu, sv, o);
    __syncthreads();
    if ((tid & 31) == 0) red[tid >> 5] = sv;
    __syncthreads();
    float sum = 0.f;
#pragma unroll
    for (int i = 0; i < 8; i++) sum += red[i];
    if (tid < 100) sa[tid] = e / sum;
    __syncthreads();
    const float* vb = Z + 1024 + h * 256;
    float acc = 0.f;
#pragma unroll 4
    for (int m = 0; m < 100; m++) acc += sa[m] * vb[m * 2048 + tid];
    O[n * 1024 + h * 256 + tid] = acc;
}

// ---------------- fold kernels ----------------
// z = zp0 + zp1   (51200 float4)
__global__ void foldZ(float4* __restrict__ z, const float4* __restrict__ zp) {
    int i = blockIdx.x * blockDim.x + threadIdx.x;
    if (i < 51200) {
        float4 a = zp[i], b = zp[i + 51200];
        z[i] = make_float4(a.x + b.x, a.y + b.y, a.z + b.z, a.w + b.w);
    }
}
// t = relu(tp0 + tp1 + b1)   (51200 float4)
__global__ void foldT(float4* __restrict__ t, const float4* __restrict__ tp,
                      const float* __restrict__ b1) {
    int i = blockIdx.x * blockDim.x + threadIdx.x;
    if (i < 51200) {
        float4 a = tp[i], b = tp[i + 51200];
        float4 bb = *(const float4*)(b1 + ((i << 2) & 2047));
        t[i] = make_float4(fmaxf(a.x + b.x + bb.x, 0.f), fmaxf(a.y + b.y + bb.y, 0.f),
                           fmaxf(a.z + b.z + bb.z, 0.f), fmaxf(a.w + b.w + bb.w, 0.f));
    }
}
// h += sum of 8 partials (+bias)
template <bool HASB>
__global__ void redAdd8(float* __restrict__ h, const float* __restrict__ part,
                        const float* __restrict__ bias) {
    int i = blockIdx.x * blockDim.x + threadIdx.x;
    if (i < 51200) {
        float s = 0.f;
#pragma unroll
        for (int j = 0; j < 8; j++) s += part[i + j * 51200];
        if (HASB) s += bias[i & 511];
        h[i] += s;
    }
}

// ---------------- host launcher ----------------
extern "C" void kernel_launch(void* const* d_in, const int* in_sizes, int n_in,
                              void* d_out, int out_size) {
    const float* x = (const float*)d_in[0];
    const float* cw[10];
    const float* cb[10];
    for (int i = 0; i < 10; i++) {
        cw[i] = (const float*)d_in[1 + 2 * i];
        cb[i] = (const float*)d_in[2 + 2 * i];
    }
    const float* Wq = (const float*)d_in[21];
    const float* Wk = (const float*)d_in[22];
    const float* Wv = (const float*)d_in[23];
    const float* Wo = (const float*)d_in[24];
    const float* W1 = (const float*)d_in[25];
    const float* b1 = (const float*)d_in[26];
    const float* W2 = (const float*)d_in[27];
    const float* b2 = (const float*)d_in[28];
    float* h = (float*)d_out;

    float *bufA, *bufB, *z, *zp, *o, *t, *tp, *part;
    cudaGetSymbolAddress((void**)&bufA, g_bufA);
    cudaGetSymbolAddress((void**)&bufB, g_bufB);
    cudaGetSymbolAddress((void**)&z, g_z);
    cudaGetSymbolAddress((void**)&zp, g_zp);
    cudaGetSymbolAddress((void**)&o, g_o);
    cudaGetSymbolAddress((void**)&t, g_t);
    cudaGetSymbolAddress((void**)&tp, g_tp);
    cudaGetSymbolAddress((void**)&part, g_part);

    // ---- conv stack ----
    conv1_kernel<<<100, 256>>>(x, cw[0], cb[0], bufA);
    conv_tile<8, 16, 18, 2, 8, true, 256><<<100, 256>>>(bufA, cw[1], cb[1], bufB);
    conv_tile<16, 32, 16, 4, 7, false, 224><<<100, 224>>>(bufB, cw[2], cb[2], bufA);
    conv_tile<32, 32, 14, 4, 6, true, 192><<<100, 192>>>(bufA, cw[3], cb[3], bufB);
    conv_tile<32, 64, 12, 4, 10, true, 160><<<100, 160>>>(bufB, cw[4], cb[4], bufA);
    conv_tile<64, 64, 10, 4, 8, true, 128><<<100, 128>>>(bufA, cw[5], cb[5], bufB);
    conv_tile<64, 128, 8, 4, 9, true, 128><<<100, 128>>>(bufB, cw[6], cb[6], bufA);
    conv_tile<128, 128, 6, 4, 4, true, 128><<<100, 128>>>(bufA, cw[7], cb[7], bufB);
    conv_tile<128, 256, 4, 4, 2, true, 128><<<100, 128>>>(bufB, cw[8], cb[8], bufA);
    gemmT_loc<<<dim3(16, 2), 128>>>(bufA, cw[9], cb[9], h);

    // ---- 12 encoder layers ----
    for (int l = 0; l < 12; l++) {
        const float* wq = Wq + (size_t)l * 4 * 512 * 128;
        const float* wk = Wk + (size_t)l * 4 * 512 * 128;
        const float* wv = Wv + (size_t)l * 4 * 512 * 256;
        const float* wo = Wo + (size_t)l * 1024 * 512;
        const float* w1 = W1 + (size_t)l * 512 * 2048;
        const float* bb1 = b1 + (size_t)l * 2048;
        const float* w2 = W2 + (size_t)l * 2048 * 512;
        const float* bb2 = b2 + (size_t)l * 512;

        // z = h @ [Wq|Wk|Wv]   (split-K=2 -> 256 blocks)
        qkvP<<<dim3(64, 2, 2), 128>>>(h, wq, wk, wv, zp, 256);
        foldZ<<<200, 256>>>((float4*)z, (const float4*)zp);
        attn_kernel<<<dim3(100, 4), 256>>>(z, o);
        // h += O @ Wo   (split-K=8 -> 256 blocks)
        gemmP<<<dim3(16, 2, 8), 128>>>(o, wo, part, 100, 1024, 512, 512, 128, 51200LL);
        redAdd8<false><<<200, 256>>>(h, part, nullptr);
        // t = relu(h @ W1 + b1)   (split-K=2 -> 256 blocks)
        gemmP<<<dim3(64, 2, 2), 128>>>(h, w1, tp, 100, 512, 2048, 2048, 256, 204800LL);
        foldT<<<200, 256>>>((float4*)t, (const float4*)tp, bb1);
        // h += t @ W2 + b2   (split-K=8 -> 256 blocks)
        gemmP<<<dim3(16, 2, 8), 128>>>(t, w2, part, 100, 2048, 512, 512, 256, 51200LL);
        redAdd8<true><<<200, 256>>>(h, part, bb2);
    }
}

// round 10
// speedup vs baseline: 1.4763x; 1.0451x over previous
#include <cuda_runtime.h>
#include <math.h>

// ---------------- scratch ----------------
__device__ __align__(16) float g_bufA[100 * 6400];
__device__ __align__(16) float g_bufB[100 * 4608];
__device__ __align__(16) float g_zp[4 * 100 * 2048];
__device__ __align__(16) float g_o[100 * 1024];
__device__ __align__(16) float g_t[100 * 2048];
__device__ __align__(16) float g_tp[4 * 100 * 2048];
__device__ __align__(16) float g_part[8 * 100 * 512];

__device__ __forceinline__ float4 ld4(const float* p) { return *(const float4*)p; }

// ---------------- conv1 ----------------
__global__ void conv1_kernel(const float* __restrict__ x, const float* __restrict__ w,
                             const float* __restrict__ b, float* __restrict__ out) {
    __shared__ float s_in[1200];
    __shared__ float s_w[216];
    __shared__ float s_b[8];
    const int p = blockIdx.x;
    const int r0 = 20 * (p % 10), c0 = 20 * (p / 10);
    for (int idx = threadIdx.x; idx < 1200; idx += blockDim.x) {
        int c = idx / 400, rem = idx % 400, y = rem / 20, xx = rem % 20;
        s_in[idx] = x[c * 40000 + (r0 + y) * 200 + c0 + xx];
    }
    for (int idx = threadIdx.x; idx < 216; idx += blockDim.x) s_w[idx] = w[idx];
    if (threadIdx.x < 8) s_b[threadIdx.x] = b[threadIdx.x];
    __syncthreads();
    for (int idx = threadIdx.x; idx < 8 * 324; idx += blockDim.x) {
        int oc = idx / 324, rem = idx % 324, oy = rem / 18, ox = rem % 18;
        float acc = s_b[oc];
        const float* wp = s_w + oc * 27;
#pragma unroll
        for (int ci = 0; ci < 3; ci++)
#pragma unroll
            for (int ky = 0; ky < 3; ky++)
#pragma unroll
                for (int kx = 0; kx < 3; kx++)
                    acc += s_in[ci * 400 + (oy + ky) * 20 + ox + kx] * wp[ci * 9 + ky * 3 + kx];
        out[p * 2592 + idx] = acc;
    }
}

// ---------------- conv_blk: weights staged in CIB blocks, oc split over grid.y ----------------
template <int CI, int CIB, int CO, int OCB, int SIN, int OCT, int CHUNK, bool RELU, int NT>
__global__ __launch_bounds__(NT) void conv_blk(const float* __restrict__ in,
                                               const float* __restrict__ w,
                                               const float* __restrict__ bias,
                                               float* __restrict__ out) {
    constexpr int SOUT = SIN - 2;
    constexpr int SP = SOUT * SOUT;
    constexpr int SS = SIN * SIN;
    constexpr int NSP = SP / CHUNK;
    constexpr int NOC = OCB / OCT;
    static_assert(NOC * NSP == NT, "thread count mismatch");
    static_assert(NSP * CHUNK == SP, "chunk mismatch");
    __shared__ float s_in[CI * SS];
    __shared__ float s_w[OCB * CIB * 9];
    const int p = blockIdx.x;
    const int ocb0 = blockIdx.y * OCB;
    const float* inp = in + (size_t)p * CI * SS;
    for (int i = threadIdx.x; i < CI * SS; i += NT) s_in[i] = inp[i];
    const int ocg = threadIdx.x / NSP;
    const int spg = threadIdx.x % NSP;
    const int oc0 = ocg * OCT, sp0 = spg * CHUNK;
    int off[CHUNK];
#pragma unroll
    for (int u = 0; u < CHUNK; u++) {
        int pos = sp0 + u;
        off[u] = (pos / SOUT) * SIN + (pos % SOUT);
    }
    float acc[OCT][CHUNK] = {};
#pragma unroll 1
    for (int cb = 0; cb < CI / CIB; cb++) {
        __syncthreads();
        for (int i = threadIdx.x; i < OCB * CIB * 9; i += NT) {
            int oc = i / (CIB * 9), r = i % (CIB * 9);
            s_w[i] = w[(size_t)(ocb0 + oc) * CI * 9 + cb * CIB * 9 + r];
        }
        __syncthreads();
#pragma unroll
        for (int ci = 0; ci < CIB; ci++) {
            const float* ib = s_in + (cb * CIB + ci) * SS;
            const float* wb = s_w + oc0 * (CIB * 9) + ci * 9;
#pragma unroll
            for (int k = 0; k < 9; k++) {
                const int ky = k / 3, kx = k % 3;
                float wf[OCT];
#pragma unroll
                for (int o = 0; o < OCT; o++) wf[o] = wb[o * (CIB * 9) + k];
                float xf[CHUNK];
                const float* ip = ib + ky * SIN + kx;
#pragma unroll
                for (int u = 0; u < CHUNK; u++) xf[u] = ip[off[u]];
#pragma unroll
                for (int o = 0; o < OCT; o++)
#pragma unroll
                    for (int u = 0; u < CHUNK; u++) acc[o][u] += wf[o] * xf[u];
            }
        }
    }
#pragma unroll
    for (int o = 0; o < OCT; o++) {
        float bv = bias[ocb0 + oc0 + o];
#pragma unroll
        for (int u = 0; u < CHUNK; u++) {
            float r = acc[o][u] + bv;
            if (RELU) r = fmaxf(r, 0.f);
            out[(size_t)p * CO * SP + (ocb0 + oc0 + o) * SP + sp0 + u] = r;
        }
    }
}

// ---------------- gemmT_loc (conv10 + location embedding) ----------------
__global__ __launch_bounds__(128) void gemmT_loc(const float* __restrict__ A,
                                                 const float* __restrict__ W,
                                                 const float* __restrict__ bias,
                                                 float* __restrict__ C) {
    const int M = 100;
    __shared__ __align__(16) float As[16][64];
    __shared__ __align__(16) float Bs[16][32];
    const int t = threadIdx.x;
    const int ty = t >> 3, tx = t & 7;
    const int am = t >> 2, ak4 = (t & 3) << 2;
    const int bn = t & 31, k4 = ((t >> 5) & 3) << 2;
    const int m0 = blockIdx.y * 64, n0 = blockIdx.x * 32;
    float acc[4][4] = {};
    for (int kk0 = 0; kk0 < 1024; kk0 += 16) {
        float4 a0 = make_float4(0.f, 0.f, 0.f, 0.f), a1 = a0;
        if (m0 + am < M) a0 = ld4(A + (long long)(m0 + am) * 1024 + kk0 + ak4);
        if (m0 + am + 32 < M) a1 = ld4(A + (long long)(m0 + am + 32) * 1024 + kk0 + ak4);
        As[ak4 + 0][am] = a0.x; As[ak4 + 1][am] = a0.y;
        As[ak4 + 2][am] = a0.z; As[ak4 + 3][am] = a0.w;
        As[ak4 + 0][am + 32] = a1.x; As[ak4 + 1][am + 32] = a1.y;
        As[ak4 + 2][am + 32] = a1.z; As[ak4 + 3][am + 32] = a1.w;
        float4 wv = ld4(W + (long long)(n0 + bn) * 1024 + kk0 + k4);
        Bs[k4 + 0][bn] = wv.x; Bs[k4 + 1][bn] = wv.y;
        Bs[k4 + 2][bn] = wv.z; Bs[k4 + 3][bn] = wv.w;
        __syncthreads();
#pragma unroll
        for (int kk = 0; kk < 16; kk++) {
            float4 a4 = *(const float4*)(&As[kk][ty << 2]);
            float4 b4 = *(const float4*)(&Bs[kk][tx << 2]);
            acc[0][0] += a4.x * b4.x; acc[0][1] += a4.x * b4.y; acc[0][2] += a4.x * b4.z; acc[0][3] += a4.x * b4.w;
            acc[1][0] += a4.y * b4.x; acc[1][1] += a4.y * b4.y; acc[1][2] += a4.y * b4.z; acc[1][3] += a4.y * b4.w;
            acc[2][0] += a4.z * b4.x; acc[2][1] += a4.z * b4.y; acc[2][2] += a4.z * b4.z; acc[2][3] += a4.z * b4.w;
            acc[3][0] += a4.w * b4.x; acc[3][1] += a4.w * b4.y; acc[3][2] += a4.w * b4.z; acc[3][3] += a4.w * b4.w;
        }
        __syncthreads();
    }
#pragma unroll
    for (int i = 0; i < 4; i++) {
        int m = m0 + (ty << 2) + i;
        if (m >= M) break;
        float pos = 20.f * (float)(m / 10);
#pragma unroll
        for (int j = 0; j < 4; j++) {
            int n = n0 + (tx << 2) + j;
            float v = acc[i][j] + bias[n];
            int kkn = (n < 256) ? n : n - 256;
            float inv = exp2f(-(2.f * (float)kkn / 256.f) * 13.287712379549449f);
            float ang = pos * inv;
            v += (n < 256) ? sinf(ang) : cosf(ang);
            C[(long long)m * 512 + n] = v;
        }
    }
}

// ---------------- double-buffered GEMM core: BK=32, 64x32 tile, 128 threads ----------------
#define FMA16(BUF)                                                                       \
    _Pragma("unroll") for (int kk = 0; kk < 32; kk++) {                                  \
        float4 a4 = *(const float4*)&As[BUF][kk][ty << 2];                               \
        float4 b4 = *(const float4*)&Bs[BUF][kk][tx << 2];                               \
        acc[0][0] += a4.x * b4.x; acc[0][1] += a4.x * b4.y; acc[0][2] += a4.x * b4.z; acc[0][3] += a4.x * b4.w; \
        acc[1][0] += a4.y * b4.x; acc[1][1] += a4.y * b4.y; acc[1][2] += a4.y * b4.z; acc[1][3] += a4.y * b4.w; \
        acc[2][0] += a4.z * b4.x; acc[2][1] += a4.z * b4.y; acc[2][2] += a4.z * b4.z; acc[2][3] += a4.z * b4.w; \
        acc[3][0] += a4.w * b4.x; acc[3][1] += a4.w * b4.y; acc[3][2] += a4.w * b4.z; acc[3][3] += a4.w * b4.w; \
    }

__device__ __forceinline__ void gemm_db(const float* A0, const float* A1, bool v0, bool v1,
                                        const float* Bb, int ldb, int k0, int nIter,
                                        float (*As)[32][64], float (*Bs)[32][32],
                                        float (&acc)[4][4]) {
    const int t = threadIdx.x;
    const int am = t >> 2, ac = (t & 3) << 3;
    const int bc = (t & 3) << 3;
    const int ty = t >> 3, tx = t & 7;
    const float4 z4 = make_float4(0.f, 0.f, 0.f, 0.f);
    {
        float4 a0 = v0 ? ld4(A0 + k0) : z4, a1 = v0 ? ld4(A0 + k0 + 4) : z4;
        float4 a2 = v1 ? ld4(A1 + k0) : z4, a3 = v1 ? ld4(A1 + k0 + 4) : z4;
        As[0][ac + 0][am] = a0.x; As[0][ac + 1][am] = a0.y;
        As[0][ac + 2][am] = a0.z; As[0][ac + 3][am] = a0.w;
        As[0][ac + 4][am] = a1.x; As[0][ac + 5][am] = a1.y;
        As[0][ac + 6][am] = a1.z; As[0][ac + 7][am] = a1.w;
        As[0][ac + 0][am + 32] = a2.x; As[0][ac + 1][am + 32] = a2.y;
        As[0][ac + 2][am + 32] = a2.z; As[0][ac + 3][am + 32] = a2.w;
        As[0][ac + 4][am + 32] = a3.x; As[0][ac + 5][am + 32] = a3.y;
        As[0][ac + 6][am + 32] = a3.z; As[0][ac + 7][am + 32] = a3.w;
        *(float4*)&Bs[0][t >> 2][bc] = ld4(Bb + (long long)k0 * ldb);
        *(float4*)&Bs[0][t >> 2][bc + 4] = ld4(Bb + (long long)k0 * ldb + 4);
    }
    __syncthreads();
    int buf = 0;
    for (int it = 0; it < nIter; ++it) {
        float4 a0, a1, a2, a3, b0, b1;
        const bool pf = (it + 1) < nIter;
        if (pf) {
            const int kn = k0 + ((it + 1) << 5);
            a0 = v0 ? ld4(A0 + kn) : z4; a1 = v0 ? ld4(A0 + kn + 4) : z4;
            a2 = v1 ? ld4(A1 + kn) : z4; a3 = v1 ? ld4(A1 + kn + 4) : z4;
            b0 = ld4(Bb + (long long)kn * ldb);
            b1 = ld4(Bb + (long long)kn * ldb + 4);
        }
        FMA16(buf)
        if (pf) {
            const int nb = buf ^ 1;
            As[nb][ac + 0][am] = a0.x; As[nb][ac + 1][am] = a0.y;
            As[nb][ac + 2][am] = a0.z; As[nb][ac + 3][am] = a0.w;
            As[nb][ac + 4][am] = a1.x; As[nb][ac + 5][am] = a1.y;
            As[nb][ac + 6][am] = a1.z; As[nb][ac + 7][am] = a1.w;
            As[nb][ac + 0][am + 32] = a2.x; As[nb][ac + 1][am + 32] = a2.y;
            As[nb][ac + 2][am + 32] = a2.z; As[nb][ac + 3][am + 32] = a2.w;
            As[nb][ac + 4][am + 32] = a3.x; As[nb][ac + 5][am + 32] = a3.y;
            As[nb][ac + 6][am + 32] = a3.z; As[nb][ac + 7][am + 32] = a3.w;
            *(float4*)&Bs[nb][t >> 2][bc] = b0;
            *(float4*)&Bs[nb][t >> 2][bc + 4] = b1;
            __syncthreads();
            buf = nb;
        }
    }
}

// plain split-K partial: C[z] = A[:, zK..] @ B[zK.., n0..]
__global__ __launch_bounds__(128) void gemmP(const float* __restrict__ A,
                                             const float* __restrict__ B,
                                             float* __restrict__ C, int M, int lda,
                                             int ldb, int ldc, int kPerZ, long long sCz) {
    __shared__ __align__(16) float As[2][32][64];
    __shared__ __align__(16) float Bs[2][32][32];
    const int m0 = blockIdx.y * 64, n0 = blockIdx.x * 32;
    const int k0 = blockIdx.z * kPerZ;
    C += (long long)blockIdx.z * sCz;
    const int t = threadIdx.x;
    const int am = t >> 2, ac = (t & 3) << 3;
    const int bc = (t & 3) << 3;
    const int ty = t >> 3, tx = t & 7;
    const bool v0 = (m0 + am) < M, v1 = (m0 + am + 32) < M;
    const float* A0 = A + (long long)(m0 + am) * lda + ac;
    const float* A1 = A + (long long)(m0 + am + 32) * lda + ac;
    const float* Bb = B + (long long)(t >> 2) * ldb + n0 + bc;
    float acc[4][4] = {};
    gemm_db(A0, A1, v0, v1, Bb, ldb, k0, kPerZ >> 5, As, Bs, acc);
#pragma unroll
    for (int i = 0; i < 4; i++) {
        int m = m0 + (ty << 2) + i;
        if (m >= M) break;
#pragma unroll
        for (int j = 0; j < 4; j++)
            C[(long long)m * ldc + n0 + (tx << 2) + j] = acc[i][j];
    }
}

// qkv split-K partial: picks Wq/Wk/Wv by n0; writes zp[z][100][2048]
__global__ __launch_bounds__(128) void qkvP(const float* __restrict__ A,
                                            const float* __restrict__ Wq,
                                            const float* __restrict__ Wk,
                                            const float* __restrict__ Wv,
                                            float* __restrict__ C, int kPerZ) {
    __shared__ __align__(16) float As[2][32][64];
    __shared__ __align__(16) float Bs[2][32][32];
    const int M = 100;
    const int m0 = blockIdx.y * 64, n0 = blockIdx.x * 32;
    const int k0 = blockIdx.z * kPerZ;
    C += (long long)blockIdx.z * 204800;
    const float* Bp; int ldb;
    if (n0 < 512)       { Bp = Wq + (n0 >> 7) * 65536 + (n0 & 127); ldb = 128; }
    else if (n0 < 1024) { int c = n0 - 512;  Bp = Wk + (c >> 7) * 65536 + (c & 127); ldb = 128; }
    else                { int c = n0 - 1024; Bp = Wv + (c >> 8) * 131072 + (c & 255); ldb = 256; }
    const int t = threadIdx.x;
    const int am = t >> 2, ac = (t & 3) << 3;
    const int bc = (t & 3) << 3;
    const int ty = t >> 3, tx = t & 7;
    const bool v0 = (m0 + am) < M, v1 = (m0 + am + 32) < M;
    const float* A0 = A + (long long)(m0 + am) * 512 + ac;
    const float* A1 = A + (long long)(m0 + am + 32) * 512 + ac;
    const float* Bb = Bp + (long long)(t >> 2) * ldb + bc;
    float acc[4][4] = {};
    gemm_db(A0, A1, v0, v1, Bb, ldb, k0, kPerZ >> 5, As, Bs, acc);
#pragma unroll
    for (int i = 0; i < 4; i++) {
        int m = m0 + (ty << 2) + i;
        if (m >= M) break;
#pragma unroll
        for (int j = 0; j < 4; j++)
            C[(long long)m * 2048 + n0 + (tx << 2) + j] = acc[i][j];
    }
}

// ---------------- attention: folds 4 qkv partials, 10 queries/block ----------------
__global__ __launch_bounds__(320) void attn2(const float* __restrict__ zp,
                                             float* __restrict__ O) {
    extern __shared__ float sm[];
    float* sK = sm;              // 100*133
    float* sQ = sm + 13300;      // 10*133
    float* sP = sm + 14630;      // 10*100
    const int qc = blockIdx.x;   // 0..9
    const int h = blockIdx.y;    // 0..3
    const int n0 = qc * 10;
    const int tid = threadIdx.x;
    const float* z0 = zp;
    const float* z1 = zp + 204800;
    const float* z2 = zp + 409600;
    const float* z3 = zp + 614400;
    for (int i = tid; i < 12800; i += 320) {
        int r = i >> 7, c = i & 127;
        int g = r * 2048 + 512 + h * 128 + c;
        sK[r * 133 + c] = z0[g] + z1[g] + z2[g] + z3[g];
    }
    for (int i = tid; i < 1280; i += 320) {
        int r = i >> 7, c = i & 127;
        int g = (n0 + r) * 2048 + h * 128 + c;
        sQ[r * 133 + c] = z0[g] + z1[g] + z2[g] + z3[g];
    }
    __syncthreads();
    {
        const int w = tid >> 5, l = tid & 31;
        const float* q = &sQ[w * 133];
        const float* k0p = &sK[l * 133];
        const float* k1p = &sK[(l + 32) * 133];
        const float* k2p = &sK[(l + 64) * 133];
        const float* k3p = (l < 4) ? &sK[(l + 96) * 133] : k0p;
        float a0 = 0.f, a1 = 0.f, a2 = 0.f, a3 = 0.f;
#pragma unroll 4
        for (int c = 0; c < 128; c++) {
            float qv = q[c];
            a0 += qv * k0p[c];
            a1 += qv * k1p[c];
            a2 += qv * k2p[c];
            a3 += qv * k3p[c];
        }
        a0 *= 0.1f; a1 *= 0.1f; a2 *= 0.1f;
        a3 = (l < 4) ? a3 * 0.1f : -1e30f;
        float mx = fmaxf(fmaxf(a0, a1), fmaxf(a2, a3));
#pragma unroll
        for (int o = 16; o; o >>= 1) mx = fmaxf(mx, __shfl_xor_sync(0xffffffffu, mx, o));
        float e0 = expf(a0 - mx), e1 = expf(a1 - mx), e2 = expf(a2 - mx);
        float e3 = (l < 4) ? expf(a3 - mx) : 0.f;
        float s = e0 + e1 + e2 + e3;
#pragma unroll
        for (int o = 16; o; o >>= 1) s += __shfl_xor_sync(0xffffffffu, s, o);
        float inv = 1.f / s;
        sP[w * 100 + l] = e0 * inv;
        sP[w * 100 + l + 32] = e1 * inv;
        sP[w * 100 + l + 64] = e2 * inv;
        if (l < 4) sP[w * 100 + l + 96] = e3 * inv;
    }
    __syncthreads();
    if (tid < 256) {
        const int c = tid;
        float acc[10];
#pragma unroll
        for (int i = 0; i < 10; i++) acc[i] = 0.f;
        for (int m = 0; m < 100; m++) {
            int g = m * 2048 + 1024 + h * 256 + c;
            float vv = z0[g] + z1[g] + z2[g] + z3[g];
            float p0 = sP[m], p1 = sP[100 + m], p2 = sP[200 + m], p3 = sP[300 + m];
            float p4 = sP[400 + m], p5 = sP[500 + m], p6 = sP[600 + m], p7 = sP[700 + m];
            float p8 = sP[800 + m], p9 = sP[900 + m];
            acc[0] += p0 * vv; acc[1] += p1 * vv; acc[2] += p2 * vv; acc[3] += p3 * vv;
            acc[4] += p4 * vv; acc[5] += p5 * vv; acc[6] += p6 * vv; acc[7] += p7 * vv;
            acc[8] += p8 * vv; acc[9] += p9 * vv;
        }
#pragma unroll
        for (int i = 0; i < 10; i++) O[(n0 + i) * 1024 + h * 256 + c] = acc[i];
    }
}

// ---------------- fold kernels ----------------
// t = relu(sum4(tp) + b1)
__global__ void foldT4(float4* __restrict__ t, const float4* __restrict__ tp,
                       const float* __restrict__ b1) {
    int i = blockIdx.x * blockDim.x + threadIdx.x;
    if (i < 51200) {
        float4 a = tp[i], b = tp[i + 51200], c = tp[i + 102400], d = tp[i + 153600];
        float4 bb = *(const float4*)(b1 + ((i << 2) & 2047));
        t[i] = make_float4(fmaxf(a.x + b.x + c.x + d.x + bb.x, 0.f),
                           fmaxf(a.y + b.y + c.y + d.y + bb.y, 0.f),
                           fmaxf(a.z + b.z + c.z + d.z + bb.z, 0.f),
                           fmaxf(a.w + b.w + c.w + d.w + bb.w, 0.f));
    }
}
// h += sum of 8 partials (+bias)
template <bool HASB>
__global__ void redAdd8(float* __restrict__ h, const float* __restrict__ part,
                        const float* __restrict__ bias) {
    int i = blockIdx.x * blockDim.x + threadIdx.x;
    if (i < 51200) {
        float s = 0.f;
#pragma unroll
        for (int j = 0; j < 8; j++) s += part[i + j * 51200];
        if (HASB) s += bias[i & 511];
        h[i] += s;
    }
}

// ---------------- host launcher ----------------
extern "C" void kernel_launch(void* const* d_in, const int* in_sizes, int n_in,
                              void* d_out, int out_size) {
    const float* x = (const float*)d_in[0];
    const float* cw[10];
    const float* cb[10];
    for (int i = 0; i < 10; i++) {
        cw[i] = (const float*)d_in[1 + 2 * i];
        cb[i] = (const float*)d_in[2 + 2 * i];
    }
    const float* Wq = (const float*)d_in[21];
    const float* Wk = (const float*)d_in[22];
    const float* Wv = (const float*)d_in[23];
    const float* Wo = (const float*)d_in[24];
    const float* W1 = (const float*)d_in[25];
    const float* b1 = (const float*)d_in[26];
    const float* W2 = (const float*)d_in[27];
    const float* b2 = (const float*)d_in[28];
    float* h = (float*)d_out;

    float *bufA, *bufB, *zp, *o, *t, *tp, *part;
    cudaGetSymbolAddress((void**)&bufA, g_bufA);
    cudaGetSymbolAddress((void**)&bufB, g_bufB);
    cudaGetSymbolAddress((void**)&zp, g_zp);
    cudaGetSymbolAddress((void**)&o, g_o);
    cudaGetSymbolAddress((void**)&t, g_t);
    cudaGetSymbolAddress((void**)&tp, g_tp);
    cudaGetSymbolAddress((void**)&part, g_part);

    const int ATTN_SMEM = (100 * 133 + 10 * 133 + 10 * 100) * 4;
    cudaFuncSetAttribute(attn2, cudaFuncAttributeMaxDynamicSharedMemorySize, ATTN_SMEM);

    // ---- conv stack ----
    conv1_kernel<<<100, 256>>>(x, cw[0], cb[0], bufA);
    conv_blk<8, 8, 16, 16, 18, 2, 8, true, 256><<<dim3(100, 1), 256>>>(bufA, cw[1], cb[1], bufB);
    conv_blk<16, 16, 32, 32, 16, 4, 7, false, 224><<<dim3(100, 1), 224>>>(bufB, cw[2], cb[2], bufA);
    conv_blk<32, 16, 32, 32, 14, 4, 6, true, 192><<<dim3(100, 1), 192>>>(bufA, cw[3], cb[3], bufB);
    conv_blk<32, 16, 64, 32, 12, 4, 5, true, 160><<<dim3(100, 2), 160>>>(bufB, cw[4], cb[4], bufA);
    conv_blk<64, 16, 64, 32, 10, 4, 4, true, 128><<<dim3(100, 2), 128>>>(bufA, cw[5], cb[5], bufB);
    conv_blk<64, 8, 128, 64, 8, 4, 3, true, 192><<<dim3(100, 2), 192>>>(bufB, cw[6], cb[6], bufA);
    conv_blk<128, 8, 128, 64, 6, 4, 2, true, 128><<<dim3(100, 2), 128>>>(bufA, cw[7], cb[7], bufB);
    conv_blk<128, 8, 256, 128, 4, 4, 1, true, 128><<<dim3(100, 2), 128>>>(bufB, cw[8], cb[8], bufA);
    gemmT_loc<<<dim3(16, 2), 128>>>(bufA, cw[9], cb[9], h);

    // ---- 12 encoder layers ----
    for (int l = 0; l < 12; l++) {
        const float* wq = Wq + (size_t)l * 4 * 512 * 128;
        const float* wk = Wk + (size_t)l * 4 * 512 * 128;
        const float* wv = Wv + (size_t)l * 4 * 512 * 256;
        const float* wo = Wo + (size_t)l * 1024 * 512;
        const float* w1 = W1 + (size_t)l * 512 * 2048;
        const float* bb1 = b1 + (size_t)l * 2048;
        const float* w2 = W2 + (size_t)l * 2048 * 512;
        const float* bb2 = b2 + (size_t)l * 512;

        // zp[z] = h @ [Wq|Wk|Wv] partials   (split-K=4 -> 512 blocks)
        qkvP<<<dim3(64, 2, 4), 128>>>(h, wq, wk, wv, zp, 128);
        // attention folds the 4 partials internally
        attn2<<<dim3(10, 4), 320, ATTN_SMEM>>>(zp, o);
        // h += O @ Wo   (split-K=8 -> 256 blocks)
        gemmP<<<dim3(16, 2, 8), 128>>>(o, wo, part, 100, 1024, 512, 512, 128, 51200LL);
        redAdd8<false><<<200, 256>>>(h, part, nullptr);
        // t = relu(h @ W1 + b1)   (split-K=4 -> 512 blocks)
        gemmP<<<dim3(64, 2, 4), 128>>>(h, w1, tp, 100, 512, 2048, 2048, 128, 204800LL);
        foldT4<<<200, 256>>>((float4*)t, (const float4*)tp, bb1);
        // h += t @ W2 + b2   (split-K=8 -> 256 blocks)
        gemmP<<<dim3(16, 2, 8), 128>>>(t, w2, part, 100, 2048, 512, 512, 256, 51200LL);
        redAdd8<true><<<200, 256>>>(h, part, bb2);
    }
}

// round 11
// speedup vs baseline: 1.5427x; 1.0450x over previous
#include <cuda_runtime.h>
#include <math.h>

// ---------------- scratch ----------------
__device__ __align__(16) float g_bufA[100 * 6400];
__device__ __align__(16) float g_bufB[100 * 4608];
__device__ __align__(16) float g_zp[4 * 100 * 2048];
__device__ __align__(16) float g_o[100 * 1024];
__device__ __align__(16) float g_t[100 * 2048];
__device__ __align__(16) float g_tp[4 * 100 * 2048];
__device__ __align__(16) float g_part[8 * 100 * 512];
__device__ int g_cnt[128];   // split-K tile counters (self-resetting)

__device__ __forceinline__ float4 ld4(const float* p) { return *(const float4*)p; }

// ---------------- conv1 ----------------
__global__ void conv1_kernel(const float* __restrict__ x, const float* __restrict__ w,
                             const float* __restrict__ b, float* __restrict__ out) {
    __shared__ float s_in[1200];
    __shared__ float s_w[216];
    __shared__ float s_b[8];
    const int p = blockIdx.x;
    const int r0 = 20 * (p % 10), c0 = 20 * (p / 10);
    for (int idx = threadIdx.x; idx < 1200; idx += blockDim.x) {
        int c = idx / 400, rem = idx % 400, y = rem / 20, xx = rem % 20;
        s_in[idx] = x[c * 40000 + (r0 + y) * 200 + c0 + xx];
    }
    for (int idx = threadIdx.x; idx < 216; idx += blockDim.x) s_w[idx] = w[idx];
    if (threadIdx.x < 8) s_b[threadIdx.x] = b[threadIdx.x];
    __syncthreads();
    for (int idx = threadIdx.x; idx < 8 * 324; idx += blockDim.x) {
        int oc = idx / 324, rem = idx % 324, oy = rem / 18, ox = rem % 18;
        float acc = s_b[oc];
        const float* wp = s_w + oc * 27;
#pragma unroll
        for (int ci = 0; ci < 3; ci++)
#pragma unroll
            for (int ky = 0; ky < 3; ky++)
#pragma unroll
                for (int kx = 0; kx < 3; kx++)
                    acc += s_in[ci * 400 + (oy + ky) * 20 + ox + kx] * wp[ci * 9 + ky * 3 + kx];
        out[p * 2592 + idx] = acc;
    }
}

// ---------------- conv_blk: weights staged in CIB blocks, oc split over grid.y ----------------
template <int CI, int CIB, int CO, int OCB, int SIN, int OCT, int CHUNK, bool RELU, int NT>
__global__ __launch_bounds__(NT) void conv_blk(const float* __restrict__ in,
                                               const float* __restrict__ w,
                                               const float* __restrict__ bias,
                                               float* __restrict__ out) {
    constexpr int SOUT = SIN - 2;
    constexpr int SP = SOUT * SOUT;
    constexpr int SS = SIN * SIN;
    constexpr int NSP = SP / CHUNK;
    constexpr int NOC = OCB / OCT;
    static_assert(NOC * NSP == NT, "thread count mismatch");
    static_assert(NSP * CHUNK == SP, "chunk mismatch");
    static_assert((CI * SS) % 4 == 0 && (CIB * 9) % 4 == 0 && (CI * 9) % 4 == 0, "vec");
    __shared__ __align__(16) float s_in[CI * SS];
    __shared__ __align__(16) float s_w[OCB * CIB * 9];
    const int p = blockIdx.x;
    const int ocb0 = blockIdx.y * OCB;
    const float* inp = in + (size_t)p * CI * SS;
    for (int i = threadIdx.x; i < CI * SS / 4; i += NT)
        ((float4*)s_in)[i] = ((const float4*)inp)[i];
    const int ocg = threadIdx.x / NSP;
    const int spg = threadIdx.x % NSP;
    const int oc0 = ocg * OCT, sp0 = spg * CHUNK;
    int off[CHUNK];
#pragma unroll
    for (int u = 0; u < CHUNK; u++) {
        int pos = sp0 + u;
        off[u] = (pos / SOUT) * SIN + (pos % SOUT);
    }
    float acc[OCT][CHUNK] = {};
#pragma unroll 1
    for (int cb = 0; cb < CI / CIB; cb++) {
        __syncthreads();
        for (int i = threadIdx.x; i < OCB * CIB * 9 / 4; i += NT) {
            int flat = i * 4;
            int oc = flat / (CIB * 9), r = flat % (CIB * 9);
            ((float4*)s_w)[i] =
                ld4(w + (size_t)(ocb0 + oc) * CI * 9 + cb * CIB * 9 + r);
        }
        __syncthreads();
#pragma unroll
        for (int ci = 0; ci < CIB; ci++) {
            const float* ib = s_in + (cb * CIB + ci) * SS;
            const float* wb = s_w + oc0 * (CIB * 9) + ci * 9;
#pragma unroll
            for (int k = 0; k < 9; k++) {
                const int ky = k / 3, kx = k % 3;
                float wf[OCT];
#pragma unroll
                for (int o = 0; o < OCT; o++) wf[o] = wb[o * (CIB * 9) + k];
                float xf[CHUNK];
                const float* ip = ib + ky * SIN + kx;
#pragma unroll
                for (int u = 0; u < CHUNK; u++) xf[u] = ip[off[u]];
#pragma unroll
                for (int o = 0; o < OCT; o++)
#pragma unroll
                    for (int u = 0; u < CHUNK; u++) acc[o][u] += wf[o] * xf[u];
            }
        }
    }
#pragma unroll
    for (int o = 0; o < OCT; o++) {
        float bv = bias[ocb0 + oc0 + o];
#pragma unroll
        for (int u = 0; u < CHUNK; u++) {
            float r = acc[o][u] + bv;
            if (RELU) r = fmaxf(r, 0.f);
            out[(size_t)p * CO * SP + (ocb0 + oc0 + o) * SP + sp0 + u] = r;
        }
    }
}

// ---------------- gemmT_loc (conv10 + location embedding) ----------------
__global__ __launch_bounds__(128) void gemmT_loc(const float* __restrict__ A,
                                                 const float* __restrict__ W,
                                                 const float* __restrict__ bias,
                                                 float* __restrict__ C) {
    const int M = 100;
    __shared__ __align__(16) float As[16][64];
    __shared__ __align__(16) float Bs[16][32];
    const int t = threadIdx.x;
    const int ty = t >> 3, tx = t & 7;
    const int am = t >> 2, ak4 = (t & 3) << 2;
    const int bn = t & 31, k4 = ((t >> 5) & 3) << 2;
    const int m0 = blockIdx.y * 64, n0 = blockIdx.x * 32;
    float acc[4][4] = {};
    for (int kk0 = 0; kk0 < 1024; kk0 += 16) {
        float4 a0 = make_float4(0.f, 0.f, 0.f, 0.f), a1 = a0;
        if (m0 + am < M) a0 = ld4(A + (long long)(m0 + am) * 1024 + kk0 + ak4);
        if (m0 + am + 32 < M) a1 = ld4(A + (long long)(m0 + am + 32) * 1024 + kk0 + ak4);
        As[ak4 + 0][am] = a0.x; As[ak4 + 1][am] = a0.y;
        As[ak4 + 2][am] = a0.z; As[ak4 + 3][am] = a0.w;
        As[ak4 + 0][am + 32] = a1.x; As[ak4 + 1][am + 32] = a1.y;
        As[ak4 + 2][am + 32] = a1.z; As[ak4 + 3][am + 32] = a1.w;
        float4 wv = ld4(W + (long long)(n0 + bn) * 1024 + kk0 + k4);
        Bs[k4 + 0][bn] = wv.x; Bs[k4 + 1][bn] = wv.y;
        Bs[k4 + 2][bn] = wv.z; Bs[k4 + 3][bn] = wv.w;
        __syncthreads();
#pragma unroll
        for (int kk = 0; kk < 16; kk++) {
            float4 a4 = *(const float4*)(&As[kk][ty << 2]);
            float4 b4 = *(const float4*)(&Bs[kk][tx << 2]);
            acc[0][0] += a4.x * b4.x; acc[0][1] += a4.x * b4.y; acc[0][2] += a4.x * b4.z; acc[0][3] += a4.x * b4.w;
            acc[1][0] += a4.y * b4.x; acc[1][1] += a4.y * b4.y; acc[1][2] += a4.y * b4.z; acc[1][3] += a4.y * b4.w;
            acc[2][0] += a4.z * b4.x; acc[2][1] += a4.z * b4.y; acc[2][2] += a4.z * b4.z; acc[2][3] += a4.z * b4.w;
            acc[3][0] += a4.w * b4.x; acc[3][1] += a4.w * b4.y; acc[3][2] += a4.w * b4.z; acc[3][3] += a4.w * b4.w;
        }
        __syncthreads();
    }
#pragma unroll
    for (int i = 0; i < 4; i++) {
        int m = m0 + (ty << 2) + i;
        if (m >= M) break;
        float pos = 20.f * (float)(m / 10);
#pragma unroll
        for (int j = 0; j < 4; j++) {
            int n = n0 + (tx << 2) + j;
            float v = acc[i][j] + bias[n];
            int kkn = (n < 256) ? n : n - 256;
            float inv = exp2f(-(2.f * (float)kkn / 256.f) * 13.287712379549449f);
            float ang = pos * inv;
            v += (n < 256) ? sinf(ang) : cosf(ang);
            C[(long long)m * 512 + n] = v;
        }
    }
}

// ---------------- double-buffered GEMM core: BK=32, 64x32 tile, 128 threads ----------------
#define FMA16(BUF)                                                                       \
    _Pragma("unroll") for (int kk = 0; kk < 32; kk++) {                                  \
        float4 a4 = *(const float4*)&As[BUF][kk][ty << 2];                               \
        float4 b4 = *(const float4*)&Bs[BUF][kk][tx << 2];                               \
        acc[0][0] += a4.x * b4.x; acc[0][1] += a4.x * b4.y; acc[0][2] += a4.x * b4.z; acc[0][3] += a4.x * b4.w; \
        acc[1][0] += a4.y * b4.x; acc[1][1] += a4.y * b4.y; acc[1][2] += a4.y * b4.z; acc[1][3] += a4.y * b4.w; \
        acc[2][0] += a4.z * b4.x; acc[2][1] += a4.z * b4.y; acc[2][2] += a4.z * b4.z; acc[2][3] += a4.z * b4.w; \
        acc[3][0] += a4.w * b4.x; acc[3][1] += a4.w * b4.y; acc[3][2] += a4.w * b4.z; acc[3][3] += a4.w * b4.w; \
    }

__device__ __forceinline__ void gemm_db(const float* A0, const float* A1, bool v0, bool v1,
                                        const float* Bb, int ldb, int k0, int nIter,
                                        float (*As)[32][64], float (*Bs)[32][32],
                                        float (&acc)[4][4]) {
    const int t = threadIdx.x;
    const int am = t >> 2, ac = (t & 3) << 3;
    const int bc = (t & 3) << 3;
    const int ty = t >> 3, tx = t & 7;
    const float4 z4 = make_float4(0.f, 0.f, 0.f, 0.f);
    {
        float4 a0 = v0 ? ld4(A0 + k0) : z4, a1 = v0 ? ld4(A0 + k0 + 4) : z4;
        float4 a2 = v1 ? ld4(A1 + k0) : z4, a3 = v1 ? ld4(A1 + k0 + 4) : z4;
        As[0][ac + 0][am] = a0.x; As[0][ac + 1][am] = a0.y;
        As[0][ac + 2][am] = a0.z; As[0][ac + 3][am] = a0.w;
        As[0][ac + 4][am] = a1.x; As[0][ac + 5][am] = a1.y;
        As[0][ac + 6][am] = a1.z; As[0][ac + 7][am] = a1.w;
        As[0][ac + 0][am + 32] = a2.x; As[0][ac + 1][am + 32] = a2.y;
        As[0][ac + 2][am + 32] = a2.z; As[0][ac + 3][am + 32] = a2.w;
        As[0][ac + 4][am + 32] = a3.x; As[0][ac + 5][am + 32] = a3.y;
        As[0][ac + 6][am + 32] = a3.z; As[0][ac + 7][am + 32] = a3.w;
        *(float4*)&Bs[0][t >> 2][bc] = ld4(Bb + (long long)k0 * ldb);
        *(float4*)&Bs[0][t >> 2][bc + 4] = ld4(Bb + (long long)k0 * ldb + 4);
    }
    __syncthreads();
    int buf = 0;
    for (int it = 0; it < nIter; ++it) {
        float4 a0, a1, a2, a3, b0, b1;
        const bool pf = (it + 1) < nIter;
        if (pf) {
            const int kn = k0 + ((it + 1) << 5);
            a0 = v0 ? ld4(A0 + kn) : z4; a1 = v0 ? ld4(A0 + kn + 4) : z4;
            a2 = v1 ? ld4(A1 + kn) : z4; a3 = v1 ? ld4(A1 + kn + 4) : z4;
            b0 = ld4(Bb + (long long)kn * ldb);
            b1 = ld4(Bb + (long long)kn * ldb + 4);
        }
        FMA16(buf)
        if (pf) {
            const int nb = buf ^ 1;
            As[nb][ac + 0][am] = a0.x; As[nb][ac + 1][am] = a0.y;
            As[nb][ac + 2][am] = a0.z; As[nb][ac + 3][am] = a0.w;
            As[nb][ac + 4][am] = a1.x; As[nb][ac + 5][am] = a1.y;
            As[nb][ac + 6][am] = a1.z; As[nb][ac + 7][am] = a1.w;
            As[nb][ac + 0][am + 32] = a2.x; As[nb][ac + 1][am + 32] = a2.y;
            As[nb][ac + 2][am + 32] = a2.z; As[nb][ac + 3][am + 32] = a2.w;
            As[nb][ac + 4][am + 32] = a3.x; As[nb][ac + 5][am + 32] = a3.y;
            As[nb][ac + 6][am + 32] = a3.z; As[nb][ac + 7][am + 32] = a3.w;
            *(float4*)&Bs[nb][t >> 2][bc] = b0;
            *(float4*)&Bs[nb][t >> 2][bc + 4] = b1;
            __syncthreads();
            buf = nb;
        }
    }
}

// ---------------- gemmR: split-K GEMM with fused deterministic reduction ----------------
// EPI 0: out[m,n] += sum   EPI 1: out[m,n] = relu(sum + bias[n])   EPI 2: out[m,n] += sum + bias[n]
template <int EPI>
__global__ __launch_bounds__(128) void gemmR(const float* __restrict__ A,
                                             const float* __restrict__ B,
                                             const float* __restrict__ bias,
                                             float* __restrict__ part,
                                             float* __restrict__ out, int M, int lda,
                                             int ldb, int N, int ldOut, int kPerZ, int Z,
                                             int nTx) {
    __shared__ __align__(16) float As[2][32][64];
    __shared__ __align__(16) float Bs[2][32][32];
    __shared__ int s_last;
    const int m0 = blockIdx.y * 64, n0 = blockIdx.x * 32;
    const int z = blockIdx.z;
    const int k0 = z * kPerZ;
    const int t = threadIdx.x;
    const int am = t >> 2, ac = (t & 3) << 3;
    const int bc = (t & 3) << 3;
    const int ty = t >> 3, tx = t & 7;
    const bool v0 = (m0 + am) < M, v1 = (m0 + am + 32) < M;
    const float* A0 = A + (long long)(m0 + am) * lda + ac;
    const float* A1 = A + (long long)(m0 + am + 32) * lda + ac;
    const float* Bb = B + (long long)(t >> 2) * ldb + n0 + bc;
    float acc[4][4] = {};
    gemm_db(A0, A1, v0, v1, Bb, ldb, k0, kPerZ >> 5, As, Bs, acc);

    // write this block's partial (float4 per row)
    const int nn = n0 + (tx << 2);
    float* pp = part + (long long)z * M * N;
#pragma unroll
    for (int i = 0; i < 4; i++) {
        int m = m0 + (ty << 2) + i;
        if (m < M)
            *(float4*)(pp + (long long)m * N + nn) =
                make_float4(acc[i][0], acc[i][1], acc[i][2], acc[i][3]);
    }
    __threadfence();
    __syncthreads();
    const int tileId = blockIdx.y * nTx + blockIdx.x;
    if (t == 0) {
        int old = atomicAdd(&g_cnt[tileId], 1);
        s_last = (old == Z - 1) ? 1 : 0;
    }
    __syncthreads();
    if (s_last) {
        __threadfence();
#pragma unroll
        for (int i = 0; i < 4; i++) {
            int m = m0 + (ty << 2) + i;
            if (m >= M) break;
            float4 s = make_float4(0.f, 0.f, 0.f, 0.f);
            for (int zz = 0; zz < Z; zz++) {
                float4 v = __ldcg((const float4*)(part + (long long)zz * M * N +
                                                  (long long)m * N + nn));
                s.x += v.x; s.y += v.y; s.z += v.z; s.w += v.w;
            }
            float* op = out + (long long)m * ldOut + nn;
            if (EPI == 0) {
                float4 o4 = ld4(op);
                o4.x += s.x; o4.y += s.y; o4.z += s.z; o4.w += s.w;
                *(float4*)op = o4;
            } else if (EPI == 1) {
                float4 b4 = ld4(bias + nn);
                *(float4*)op = make_float4(fmaxf(s.x + b4.x, 0.f), fmaxf(s.y + b4.y, 0.f),
                                           fmaxf(s.z + b4.z, 0.f), fmaxf(s.w + b4.w, 0.f));
            } else {
                float4 o4 = ld4(op);
                float4 b4 = ld4(bias + nn);
                o4.x += s.x + b4.x; o4.y += s.y + b4.y;
                o4.z += s.z + b4.z; o4.w += s.w + b4.w;
                *(float4*)op = o4;
            }
        }
        __syncthreads();
        if (t == 0) g_cnt[tileId] = 0;   // self-reset for next use
    }
}

// qkv split-K partial: picks Wq/Wk/Wv by n0; writes zp[z][100][2048]
__global__ __launch_bounds__(128) void qkvP(const float* __restrict__ A,
                                            const float* __restrict__ Wq,
                                            const float* __restrict__ Wk,
                                            const float* __restrict__ Wv,
                                            float* __restrict__ C, int kPerZ) {
    __shared__ __align__(16) float As[2][32][64];
    __shared__ __align__(16) float Bs[2][32][32];
    const int M = 100;
    const int m0 = blockIdx.y * 64, n0 = blockIdx.x * 32;
    const int k0 = blockIdx.z * kPerZ;
    C += (long long)blockIdx.z * 204800;
    const float* Bp; int ldb;
    if (n0 < 512)       { Bp = Wq + (n0 >> 7) * 65536 + (n0 & 127); ldb = 128; }
    else if (n0 < 1024) { int c = n0 - 512;  Bp = Wk + (c >> 7) * 65536 + (c & 127); ldb = 128; }
    else                { int c = n0 - 1024; Bp = Wv + (c >> 8) * 131072 + (c & 255); ldb = 256; }
    const int t = threadIdx.x;
    const int am = t >> 2, ac = (t & 3) << 3;
    const int bc = (t & 3) << 3;
    const int ty = t >> 3, tx = t & 7;
    const bool v0 = (m0 + am) < M, v1 = (m0 + am + 32) < M;
    const float* A0 = A + (long long)(m0 + am) * 512 + ac;
    const float* A1 = A + (long long)(m0 + am + 32) * 512 + ac;
    const float* Bb = Bp + (long long)(t >> 2) * ldb + bc;
    float acc[4][4] = {};
    gemm_db(A0, A1, v0, v1, Bb, ldb, k0, kPerZ >> 5, As, Bs, acc);
#pragma unroll
    for (int i = 0; i < 4; i++) {
        int m = m0 + (ty << 2) + i;
        if (m >= M) break;
#pragma unroll
        for (int j = 0; j < 4; j++)
            C[(long long)m * 2048 + n0 + (tx << 2) + j] = acc[i][j];
    }
}

// ---------------- attention: folds 4 qkv partials, 10 queries/block ----------------
__global__ __launch_bounds__(320) void attn2(const float* __restrict__ zp,
                                             float* __restrict__ O) {
    extern __shared__ float sm[];
    float* sK = sm;              // 100*133
    float* sQ = sm + 13300;      // 10*133
    float* sP = sm + 14630;      // 10*100
    const int qc = blockIdx.x;
    const int h = blockIdx.y;
    const int n0 = qc * 10;
    const int tid = threadIdx.x;
    const float* z0 = zp;
    const float* z1 = zp + 204800;
    const float* z2 = zp + 409600;
    const float* z3 = zp + 614400;
    for (int i = tid; i < 12800; i += 320) {
        int r = i >> 7, c = i & 127;
        int g = r * 2048 + 512 + h * 128 + c;
        sK[r * 133 + c] = z0[g] + z1[g] + z2[g] + z3[g];
    }
    for (int i = tid; i < 1280; i += 320) {
        int r = i >> 7, c = i & 127;
        int g = (n0 + r) * 2048 + h * 128 + c;
        sQ[r * 133 + c] = z0[g] + z1[g] + z2[g] + z3[g];
    }
    __syncthreads();
    {
        const int w = tid >> 5, l = tid & 31;
        const float* q = &sQ[w * 133];
        const float* k0p = &sK[l * 133];
        const float* k1p = &sK[(l + 32) * 133];
        const float* k2p = &sK[(l + 64) * 133];
        const float* k3p = (l < 4) ? &sK[(l + 96) * 133] : k0p;
        float a0 = 0.f, a1 = 0.f, a2 = 0.f, a3 = 0.f;
#pragma unroll 4
        for (int c = 0; c < 128; c++) {
            float qv = q[c];
            a0 += qv * k0p[c];
            a1 += qv * k1p[c];
            a2 += qv * k2p[c];
            a3 += qv * k3p[c];
        }
        a0 *= 0.1f; a1 *= 0.1f; a2 *= 0.1f;
        a3 = (l < 4) ? a3 * 0.1f : -1e30f;
        float mx = fmaxf(fmaxf(a0, a1), fmaxf(a2, a3));
#pragma unroll
        for (int o = 16; o; o >>= 1) mx = fmaxf(mx, __shfl_xor_sync(0xffffffffu, mx, o));
        float e0 = expf(a0 - mx), e1 = expf(a1 - mx), e2 = expf(a2 - mx);
        float e3 = (l < 4) ? expf(a3 - mx) : 0.f;
        float s = e0 + e1 + e2 + e3;
#pragma unroll
        for (int o = 16; o; o >>= 1) s += __shfl_xor_sync(0xffffffffu, s, o);
        float inv = 1.f / s;
        sP[w * 100 + l] = e0 * inv;
        sP[w * 100 + l + 32] = e1 * inv;
        sP[w * 100 + l + 64] = e2 * inv;
        if (l < 4) sP[w * 100 + l + 96] = e3 * inv;
    }
    __syncthreads();
    if (tid < 256) {
        const int c = tid;
        float acc[10];
#pragma unroll
        for (int i = 0; i < 10; i++) acc[i] = 0.f;
        for (int m = 0; m < 100; m++) {
            int g = m * 2048 + 1024 + h * 256 + c;
            float vv = z0[g] + z1[g] + z2[g] + z3[g];
            float p0 = sP[m], p1 = sP[100 + m], p2 = sP[200 + m], p3 = sP[300 + m];
            float p4 = sP[400 + m], p5 = sP[500 + m], p6 = sP[600 + m], p7 = sP[700 + m];
            float p8 = sP[800 + m], p9 = sP[900 + m];
            acc[0] += p0 * vv; acc[1] += p1 * vv; acc[2] += p2 * vv; acc[3] += p3 * vv;
            acc[4] += p4 * vv; acc[5] += p5 * vv; acc[6] += p6 * vv; acc[7] += p7 * vv;
            acc[8] += p8 * vv; acc[9] += p9 * vv;
        }
#pragma unroll
        for (int i = 0; i < 10; i++) O[(n0 + i) * 1024 + h * 256 + c] = acc[i];
    }
}

// ---------------- host launcher ----------------
extern "C" void kernel_launch(void* const* d_in, const int* in_sizes, int n_in,
                              void* d_out, int out_size) {
    const float* x = (const float*)d_in[0];
    const float* cw[10];
    const float* cb[10];
    for (int i = 0; i < 10; i++) {
        cw[i] = (const float*)d_in[1 + 2 * i];
        cb[i] = (const float*)d_in[2 + 2 * i];
    }
    const float* Wq = (const float*)d_in[21];
    const float* Wk = (const float*)d_in[22];
    const float* Wv = (const float*)d_in[23];
    const float* Wo = (const float*)d_in[24];
    const float* W1 = (const float*)d_in[25];
    const float* b1 = (const float*)d_in[26];
    const float* W2 = (const float*)d_in[27];
    const float* b2 = (const float*)d_in[28];
    float* h = (float*)d_out;

    float *bufA, *bufB, *zp, *o, *t, *tp, *part;
    cudaGetSymbolAddress((void**)&bufA, g_bufA);
    cudaGetSymbolAddress((void**)&bufB, g_bufB);
    cudaGetSymbolAddress((void**)&zp, g_zp);
    cudaGetSymbolAddress((void**)&o, g_o);
    cudaGetSymbolAddress((void**)&t, g_t);
    cudaGetSymbolAddress((void**)&tp, g_tp);
    cudaGetSymbolAddress((void**)&part, g_part);

    const int ATTN_SMEM = (100 * 133 + 10 * 133 + 10 * 100) * 4;
    cudaFuncSetAttribute(attn2, cudaFuncAttributeMaxDynamicSharedMemorySize, ATTN_SMEM);

    // ---- conv stack ----
    conv1_kernel<<<100, 256>>>(x, cw[0], cb[0], bufA);
    conv_blk<8, 8, 16, 8, 18, 2, 8, true, 128><<<dim3(100, 2), 128>>>(bufA, cw[1], cb[1], bufB);
    conv_blk<16, 16, 32, 16, 16, 4, 7, false, 112><<<dim3(100, 2), 112>>>(bufB, cw[2], cb[2], bufA);
    conv_blk<32, 16, 32, 16, 14, 4, 6, true, 96><<<dim3(100, 2), 96>>>(bufA, cw[3], cb[3], bufB);
    conv_blk<32, 16, 64, 32, 12, 4, 5, true, 160><<<dim3(100, 2), 160>>>(bufB, cw[4], cb[4], bufA);
    conv_blk<64, 16, 64, 32, 10, 4, 4, true, 128><<<dim3(100, 2), 128>>>(bufA, cw[5], cb[5], bufB);
    conv_blk<64, 8, 128, 64, 8, 4, 3, true, 192><<<dim3(100, 2), 192>>>(bufB, cw[6], cb[6], bufA);
    conv_blk<128, 8, 128, 64, 6, 4, 2, true, 128><<<dim3(100, 2), 128>>>(bufA, cw[7], cb[7], bufB);
    conv_blk<128, 8, 256, 128, 4, 4, 1, true, 128><<<dim3(100, 2), 128>>>(bufB, cw[8], cb[8], bufA);
    gemmT_loc<<<dim3(16, 2), 128>>>(bufA, cw[9], cb[9], h);

    // ---- 12 encoder layers (5 launches each) ----
    for (int l = 0; l < 12; l++) {
        const float* wq = Wq + (size_t)l * 4 * 512 * 128;
        const float* wk = Wk + (size_t)l * 4 * 512 * 128;
        const float* wv = Wv + (size_t)l * 4 * 512 * 256;
        const float* wo = Wo + (size_t)l * 1024 * 512;
        const float* w1 = W1 + (size_t)l * 512 * 2048;
        const float* bb1 = b1 + (size_t)l * 2048;
        const float* w2 = W2 + (size_t)l * 2048 * 512;
        const float* bb2 = b2 + (size_t)l * 512;

        // zp[z] = h @ [Wq|Wk|Wv] partials   (split-K=4 -> 512 blocks)
        qkvP<<<dim3(64, 2, 4), 128>>>(h, wq, wk, wv, zp, 128);
        // attention folds the 4 partials internally
        attn2<<<dim3(10, 4), 320, ATTN_SMEM>>>(zp, o);
        // h += O @ Wo   (split-K=8, fused reduce)
        gemmR<0><<<dim3(16, 2, 8), 128>>>(o, wo, nullptr, part, h,
                                          100, 1024, 512, 512, 512, 128, 8, 16);
        // t = relu(h @ W1 + b1)   (split-K=4, fused reduce)
        gemmR<1><<<dim3(64, 2, 4), 128>>>(h, w1, bb1, tp, t,
                                          100, 512, 2048, 2048, 2048, 128, 4, 64);
        // h += t @ W2 + b2   (split-K=8, fused reduce)
        gemmR<2><<<dim3(16, 2, 8), 128>>>(t, w2, bb2, part, h,
                                          100, 2048, 512, 512, 512, 256, 8, 16);
    }
}

// round 13
// speedup vs baseline: 1.6524x; 1.0711x over previous
#include <cuda_runtime.h>
#include <stdint.h>
#include <math.h>

// ---------------- scratch ----------------
__device__ __align__(16) float g_bufA[100 * 6400];
__device__ __align__(16) float g_bufB[100 * 4608];
__device__ __align__(16) float g_zp[4 * 100 * 2048];
__device__ __align__(16) float g_o[100 * 1024];
__device__ __align__(16) float g_t[100 * 2048];
__device__ __align__(16) float g_tp[4 * 100 * 2048];
__device__ __align__(16) float g_part[8 * 100 * 512];
__device__ int g_cnt[128];   // split-K tile counters (self-resetting)

__device__ __forceinline__ float4 ld4(const float* p) { return *(const float4*)p; }

__device__ __forceinline__ uint32_t tf32c(float x) {
    uint32_t u;
    asm("cvt.rna.tf32.f32 %0, %1;" : "=r"(u) : "f"(x));
    return u;
}
__device__ __forceinline__ float4 tf32c4(float4 v) {
    return make_float4(__uint_as_float(tf32c(v.x)), __uint_as_float(tf32c(v.y)),
                       __uint_as_float(tf32c(v.z)), __uint_as_float(tf32c(v.w)));
}
__device__ __forceinline__ void mma_tf32(float* c, uint32_t a0, uint32_t a1, uint32_t a2,
                                         uint32_t a3, uint32_t b0, uint32_t b1) {
    asm volatile(
        "mma.sync.aligned.m16n8k8.row.col.f32.tf32.tf32.f32 "
        "{%0,%1,%2,%3}, {%4,%5,%6,%7}, {%8,%9}, {%0,%1,%2,%3};"
        : "+f"(c[0]), "+f"(c[1]), "+f"(c[2]), "+f"(c[3])
        : "r"(a0), "r"(a1), "r"(a2), "r"(a3), "r"(b0), "r"(b1));
}

// ---------------- conv1 ----------------
__global__ void conv1_kernel(const float* __restrict__ x, const float* __restrict__ w,
                             const float* __restrict__ b, float* __restrict__ out) {
    __shared__ float s_in[1200];
    __shared__ float s_w[216];
    __shared__ float s_b[8];
    const int p = blockIdx.x;
    const int r0 = 20 * (p % 10), c0 = 20 * (p / 10);
    for (int idx = threadIdx.x; idx < 1200; idx += blockDim.x) {
        int c = idx / 400, rem = idx % 400, y = rem / 20, xx = rem % 20;
        s_in[idx] = x[c * 40000 + (r0 + y) * 200 + c0 + xx];
    }
    for (int idx = threadIdx.x; idx < 216; idx += blockDim.x) s_w[idx] = w[idx];
    if (threadIdx.x < 8) s_b[threadIdx.x] = b[threadIdx.x];
    __syncthreads();
    for (int idx = threadIdx.x; idx < 8 * 324; idx += blockDim.x) {
        int oc = idx / 324, rem = idx % 324, oy = rem / 18, ox = rem % 18;
        float acc = s_b[oc];
        const float* wp = s_w + oc * 27;
#pragma unroll
        for (int ci = 0; ci < 3; ci++)
#pragma unroll
            for (int ky = 0; ky < 3; ky++)
#pragma unroll
                for (int kx = 0; kx < 3; kx++)
                    acc += s_in[ci * 400 + (oy + ky) * 20 + ox + kx] * wp[ci * 9 + ky * 3 + kx];
        out[p * 2592 + idx] = acc;
    }
}

// ---------------- conv_blk (unchanged) ----------------
template <int CI, int CIB, int CO, int OCB, int SIN, int OCT, int CHUNK, bool RELU, int NT>
__global__ __launch_bounds__(NT) void conv_blk(const float* __restrict__ in,
                                               const float* __restrict__ w,
                                               const float* __restrict__ bias,
                                               float* __restrict__ out) {
    constexpr int SOUT = SIN - 2;
    constexpr int SP = SOUT * SOUT;
    constexpr int SS = SIN * SIN;
    constexpr int NSP = SP / CHUNK;
    constexpr int NOC = OCB / OCT;
    static_assert(NOC * NSP == NT, "thread count mismatch");
    static_assert(NSP * CHUNK == SP, "chunk mismatch");
    __shared__ __align__(16) float s_in[CI * SS];
    __shared__ __align__(16) float s_w[OCB * CIB * 9];
    const int p = blockIdx.x;
    const int ocb0 = blockIdx.y * OCB;
    const float* inp = in + (size_t)p * CI * SS;
    for (int i = threadIdx.x; i < CI * SS / 4; i += NT)
        ((float4*)s_in)[i] = ((const float4*)inp)[i];
    const int ocg = threadIdx.x / NSP;
    const int spg = threadIdx.x % NSP;
    const int oc0 = ocg * OCT, sp0 = spg * CHUNK;
    int off[CHUNK];
#pragma unroll
    for (int u = 0; u < CHUNK; u++) {
        int pos = sp0 + u;
        off[u] = (pos / SOUT) * SIN + (pos % SOUT);
    }
    float acc[OCT][CHUNK] = {};
#pragma unroll 1
    for (int cb = 0; cb < CI / CIB; cb++) {
        __syncthreads();
        for (int i = threadIdx.x; i < OCB * CIB * 9 / 4; i += NT) {
            int flat = i * 4;
            int oc = flat / (CIB * 9), r = flat % (CIB * 9);
            ((float4*)s_w)[i] = ld4(w + (size_t)(ocb0 + oc) * CI * 9 + cb * CIB * 9 + r);
        }
        __syncthreads();
#pragma unroll
        for (int ci = 0; ci < CIB; ci++) {
            const float* ib = s_in + (cb * CIB + ci) * SS;
            const float* wb = s_w + oc0 * (CIB * 9) + ci * 9;
#pragma unroll
            for (int k = 0; k < 9; k++) {
                const int ky = k / 3, kx = k % 3;
                float wf[OCT];
#pragma unroll
                for (int o = 0; o < OCT; o++) wf[o] = wb[o * (CIB * 9) + k];
                float xf[CHUNK];
                const float* ip = ib + ky * SIN + kx;
#pragma unroll
                for (int u = 0; u < CHUNK; u++) xf[u] = ip[off[u]];
#pragma unroll
                for (int o = 0; o < OCT; o++)
#pragma unroll
                    for (int u = 0; u < CHUNK; u++) acc[o][u] += wf[o] * xf[u];
            }
        }
    }
#pragma unroll
    for (int o = 0; o < OCT; o++) {
        float bv = bias[ocb0 + oc0 + o];
#pragma unroll
        for (int u = 0; u < CHUNK; u++) {
            float r = acc[o][u] + bv;
            if (RELU) r = fmaxf(r, 0.f);
            out[(size_t)p * CO * SP + (ocb0 + oc0 + o) * SP + sp0 + u] = r;
        }
    }
}

// ---------------- gemmT_loc (conv10 + location embedding, fp32, runs once) ----------------
__global__ __launch_bounds__(128) void gemmT_loc(const float* __restrict__ A,
                                                 const float* __restrict__ W,
                                                 const float* __restrict__ bias,
                                                 float* __restrict__ C) {
    const int M = 100;
    __shared__ __align__(16) float As[16][64];
    __shared__ __align__(16) float Bs[16][32];
    const int t = threadIdx.x;
    const int ty = t >> 3, tx = t & 7;
    const int am = t >> 2, ak4 = (t & 3) << 2;
    const int bn = t & 31, k4 = ((t >> 5) & 3) << 2;
    const int m0 = blockIdx.y * 64, n0 = blockIdx.x * 32;
    float acc[4][4] = {};
    for (int kk0 = 0; kk0 < 1024; kk0 += 16) {
        float4 a0 = make_float4(0.f, 0.f, 0.f, 0.f), a1 = a0;
        if (m0 + am < M) a0 = ld4(A + (long long)(m0 + am) * 1024 + kk0 + ak4);
        if (m0 + am + 32 < M) a1 = ld4(A + (long long)(m0 + am + 32) * 1024 + kk0 + ak4);
        As[ak4 + 0][am] = a0.x; As[ak4 + 1][am] = a0.y;
        As[ak4 + 2][am] = a0.z; As[ak4 + 3][am] = a0.w;
        As[ak4 + 0][am + 32] = a1.x; As[ak4 + 1][am + 32] = a1.y;
        As[ak4 + 2][am + 32] = a1.z; As[ak4 + 3][am + 32] = a1.w;
        float4 wv = ld4(W + (long long)(n0 + bn) * 1024 + kk0 + k4);
        Bs[k4 + 0][bn] = wv.x; Bs[k4 + 1][bn] = wv.y;
        Bs[k4 + 2][bn] = wv.z; Bs[k4 + 3][bn] = wv.w;
        __syncthreads();
#pragma unroll
        for (int kk = 0; kk < 16; kk++) {
            float4 a4 = *(const float4*)(&As[kk][ty << 2]);
            float4 b4 = *(const float4*)(&Bs[kk][tx << 2]);
            acc[0][0] += a4.x * b4.x; acc[0][1] += a4.x * b4.y; acc[0][2] += a4.x * b4.z; acc[0][3] += a4.x * b4.w;
            acc[1][0] += a4.y * b4.x; acc[1][1] += a4.y * b4.y; acc[1][2] += a4.y * b4.z; acc[1][3] += a4.y * b4.w;
            acc[2][0] += a4.z * b4.x; acc[2][1] += a4.z * b4.y; acc[2][2] += a4.z * b4.z; acc[2][3] += a4.z * b4.w;
            acc[3][0] += a4.w * b4.x; acc[3][1] += a4.w * b4.y; acc[3][2] += a4.w * b4.z; acc[3][3] += a4.w * b4.w;
        }
        __syncthreads();
    }
#pragma unroll
    for (int i = 0; i < 4; i++) {
        int m = m0 + (ty << 2) + i;
        if (m >= M) break;
        float pos = 20.f * (float)(m / 10);
#pragma unroll
        for (int j = 0; j < 4; j++) {
            int n = n0 + (tx << 2) + j;
            float v = acc[i][j] + bias[n];
            int kkn = (n < 256) ? n : n - 256;
            float inv = exp2f(-(2.f * (float)kkn / 256.f) * 13.287712379549449f);
            float ang = pos * inv;
            v += (n < 256) ? sinf(ang) : cosf(ang);
            C[(long long)m * 512 + n] = v;
        }
    }
}

// ---------------- tf32 MMA GEMM core: BK=32, 64x32 tile, 128 threads (4 warps) ----------------
// As[buf][64][36] m-major k-contig (tf32 bits); Bs[buf][32][36] k-major n-contig.
// Warp w: rows m0+w*16..+15, all 32 cols. acc[nb][4] per mma fragment layout.
struct MmaSmem {
    float As[2][64][36];
    float Bs[2][32][36];
};

#define MMA_STAGE(BUF, AA0, AA1, AA2, AA3, BB0, BB1)                                     \
    {                                                                                    \
        float4 c0 = tf32c4(AA0), c1 = tf32c4(AA1), c2 = tf32c4(AA2), c3 = tf32c4(AA3);   \
        *(float4*)&S->As[BUF][am][ac] = c0;                                              \
        *(float4*)&S->As[BUF][am][ac + 4] = c1;                                          \
        *(float4*)&S->As[BUF][am + 32][ac] = c2;                                         \
        *(float4*)&S->As[BUF][am + 32][ac + 4] = c3;                                     \
        *(float4*)&S->Bs[BUF][bk][bc] = tf32c4(BB0);                                     \
        *(float4*)&S->Bs[BUF][bk][bc + 4] = tf32c4(BB1);                                 \
    }

#define MMA_COMPUTE(BUF)                                                                 \
    _Pragma("unroll") for (int ks = 0; ks < 4; ks++) {                                   \
        const int kb = ks * 8;                                                           \
        uint32_t a0 = __float_as_uint(S->As[BUF][w16 + g][kb + tig]);                    \
        uint32_t a1 = __float_as_uint(S->As[BUF][w16 + g + 8][kb + tig]);                \
        uint32_t a2 = __float_as_uint(S->As[BUF][w16 + g][kb + tig + 4]);                \
        uint32_t a3 = __float_as_uint(S->As[BUF][w16 + g + 8][kb + tig + 4]);            \
        _Pragma("unroll") for (int nb = 0; nb < 4; nb++) {                               \
            uint32_t b0 = __float_as_uint(S->Bs[BUF][kb + tig][nb * 8 + g]);             \
            uint32_t b1 = __float_as_uint(S->Bs[BUF][kb + tig + 4][nb * 8 + g]);         \
            mma_tf32(acc[nb], a0, a1, a2, a3, b0, b1);                                   \
        }                                                                                \
    }

__device__ __forceinline__ void gemm_mma(const float* A0, const float* A1, bool v0, bool v1,
                                         const float* Bb, int ldb, int k0, int nIter,
                                         MmaSmem* S, float (&acc)[4][4]) {
    const int t = threadIdx.x;
    const int am = t >> 2, ac = (t & 3) << 3;
    const int bk = t >> 2, bc = (t & 3) << 3;
    const int w16 = (t >> 5) << 4;
    const int g = (t & 31) >> 2, tig = t & 3;
    const float4 z4 = make_float4(0.f, 0.f, 0.f, 0.f);
    {
        float4 a0 = v0 ? ld4(A0 + k0) : z4, a1 = v0 ? ld4(A0 + k0 + 4) : z4;
        float4 a2 = v1 ? ld4(A1 + k0) : z4, a3 = v1 ? ld4(A1 + k0 + 4) : z4;
        float4 b0 = ld4(Bb + (long long)k0 * ldb);
        float4 b1 = ld4(Bb + (long long)k0 * ldb + 4);
        MMA_STAGE(0, a0, a1, a2, a3, b0, b1)
    }
    __syncthreads();
    int buf = 0;
    for (int it = 0; it < nIter; ++it) {
        float4 a0, a1, a2, a3, b0, b1;
        const bool pf = (it + 1) < nIter;
        if (pf) {
            const int kn = k0 + ((it + 1) << 5);
            a0 = v0 ? ld4(A0 + kn) : z4; a1 = v0 ? ld4(A0 + kn + 4) : z4;
            a2 = v1 ? ld4(A1 + kn) : z4; a3 = v1 ? ld4(A1 + kn + 4) : z4;
            b0 = ld4(Bb + (long long)kn * ldb);
            b1 = ld4(Bb + (long long)kn * ldb + 4);
        }
        MMA_COMPUTE(buf)
        if (pf) {
            const int nb2 = buf ^ 1;
            __syncthreads();   // everyone done reading buf^1 from prior round
            MMA_STAGE(nb2, a0, a1, a2, a3, b0, b1)
            __syncthreads();
            buf = nb2;
        }
    }
}

// ---------------- gemmR: split-K tf32 GEMM with fused deterministic reduction ----------------
// EPI 0: out += sum   EPI 1: out = relu(sum+bias)   EPI 2: out += sum + bias
template <int EPI>
__global__ __launch_bounds__(128) void gemmR(const float* __restrict__ A,
                                             const float* __restrict__ B,
                                             const float* __restrict__ bias,
                                             float* __restrict__ part,
                                             float* __restrict__ out, int M, int lda,
                                             int ldb, int N, int ldOut, int kPerZ, int Z,
                                             int nTx) {
    __shared__ MmaSmem S_;
    __shared__ int s_last;
    MmaSmem* S = &S_;
    const int m0 = blockIdx.y * 64, n0 = blockIdx.x * 32;
    const int z = blockIdx.z;
    const int k0 = z * kPerZ;
    const int t = threadIdx.x;
    const int am = t >> 2, ac = (t & 3) << 3;
    const int bc = (t & 3) << 3;
    const int w16 = (t >> 5) << 4;
    const int g = (t & 31) >> 2, tig = t & 3;
    const bool v0 = (m0 + am) < M, v1 = (m0 + am + 32) < M;
    const float* A0 = A + (long long)(m0 + am) * lda + ac;
    const float* A1 = A + (long long)(m0 + am + 32) * lda + ac;
    const float* Bb = B + (long long)(t >> 2) * ldb + n0 + bc;
    float acc[4][4] = {};
    gemm_mma(A0, A1, v0, v1, Bb, ldb, k0, kPerZ >> 5, S, acc);

    // partial write (float2 per fragment row)
    float* pp = part + (long long)z * M * N;
    const int r0 = m0 + w16 + g, r1 = r0 + 8;
#pragma unroll
    for (int nb = 0; nb < 4; nb++) {
        const int col = n0 + nb * 8 + tig * 2;
        if (r0 < M) *(float2*)(pp + (long long)r0 * N + col) = make_float2(acc[nb][0], acc[nb][1]);
        if (r1 < M) *(float2*)(pp + (long long)r1 * N + col) = make_float2(acc[nb][2], acc[nb][3]);
    }
    __threadfence();
    __syncthreads();
    const int tileId = blockIdx.y * nTx + blockIdx.x;
    if (t == 0) {
        int old = atomicAdd(&g_cnt[tileId], 1);
        s_last = (old == Z - 1) ? 1 : 0;
    }
    __syncthreads();
    if (s_last) {
        __threadfence();
#pragma unroll
        for (int nb = 0; nb < 4; nb++) {
            const int col = n0 + nb * 8 + tig * 2;
#pragma unroll
            for (int half = 0; half < 2; half++) {
                const int m = (half == 0) ? r0 : r1;
                if (m >= M) continue;
                float2 s = make_float2(0.f, 0.f);
                for (int zz = 0; zz < Z; zz++) {
                    float2 v = __ldcg((const float2*)(part + (long long)zz * M * N +
                                                      (long long)m * N + col));
                    s.x += v.x; s.y += v.y;
                }
                float* op = out + (long long)m * ldOut + col;
                if (EPI == 0) {
                    op[0] += s.x; op[1] += s.y;
                } else if (EPI == 1) {
                    float2 b2 = *(const float2*)(bias + col);
                    op[0] = fmaxf(s.x + b2.x, 0.f);
                    op[1] = fmaxf(s.y + b2.y, 0.f);
                } else {
                    float2 b2 = *(const float2*)(bias + col);
                    op[0] += s.x + b2.x;
                    op[1] += s.y + b2.y;
                }
            }
        }
        __syncthreads();
        if (t == 0) g_cnt[tileId] = 0;
    }
}

// qkv split-K tf32 partial: picks Wq/Wk/Wv by n0; writes zp[z][100][2048]
__global__ __launch_bounds__(128) void qkvP(const float* __restrict__ A,
                                            const float* __restrict__ Wq,
                                            const float* __restrict__ Wk,
                                            const float* __restrict__ Wv,
                                            float* __restrict__ C, int kPerZ) {
    __shared__ MmaSmem S_;
    MmaSmem* S = &S_;
    const int M = 100;
    const int m0 = blockIdx.y * 64, n0 = blockIdx.x * 32;
    const int k0 = blockIdx.z * kPerZ;
    C += (long long)blockIdx.z * 204800;
    const float* Bp; int ldb;
    if (n0 < 512)       { Bp = Wq + (n0 >> 7) * 65536 + (n0 & 127); ldb = 128; }
    else if (n0 < 1024) { int c = n0 - 512;  Bp = Wk + (c >> 7) * 65536 + (c & 127); ldb = 128; }
    else                { int c = n0 - 1024; Bp = Wv + (c >> 8) * 131072 + (c & 255); ldb = 256; }
    const int t = threadIdx.x;
    const int am = t >> 2, ac = (t & 3) << 3;
    const int bc = (t & 3) << 3;
    const int w16 = (t >> 5) << 4;
    const int g = (t & 31) >> 2, tig = t & 3;
    const bool v0 = (m0 + am) < M, v1 = (m0 + am + 32) < M;
    const float* A0 = A + (long long)(m0 + am) * 512 + ac;
    const float* A1 = A + (long long)(m0 + am + 32) * 512 + ac;
    const float* Bb = Bp + (long long)(t >> 2) * ldb + bc;
    float acc[4][4] = {};
    gemm_mma(A0, A1, v0, v1, Bb, ldb, k0, kPerZ >> 5, S, acc);
    const int r0 = m0 + w16 + g, r1 = r0 + 8;
#pragma unroll
    for (int nb = 0; nb < 4; nb++) {
        const int col = n0 + nb * 8 + tig * 2;
        if (r0 < M) *(float2*)(C + (long long)r0 * 2048 + col) = make_float2(acc[nb][0], acc[nb][1]);
        if (r1 < M) *(float2*)(C + (long long)r1 * 2048 + col) = make_float2(acc[nb][2], acc[nb][3]);
    }
}

// ---------------- attention: folds 4 qkv partials, 10 queries/block (fp32) ----------------
__global__ __launch_bounds__(320) void attn2(const float* __restrict__ zp,
                                             float* __restrict__ O) {
    extern __shared__ float sm[];
    float* sK = sm;              // 100*133
    float* sQ = sm + 13300;      // 10*133
    float* sP = sm + 14630;      // 10*100
    const int qc = blockIdx.x;
    const int h = blockIdx.y;
    const int n0 = qc * 10;
    const int tid = threadIdx.x;
    const float* z0 = zp;
    const float* z1 = zp + 204800;
    const float* z2 = zp + 409600;
    const float* z3 = zp + 614400;
    for (int i = tid; i < 12800; i += 320) {
        int r = i >> 7, c = i & 127;
        int g = r * 2048 + 512 + h * 128 + c;
        sK[r * 133 + c] = z0[g] + z1[g] + z2[g] + z3[g];
    }
    for (int i = tid; i < 1280; i += 320) {
        int r = i >> 7, c = i & 127;
        int g = (n0 + r) * 2048 + h * 128 + c;
        sQ[r * 133 + c] = z0[g] + z1[g] + z2[g] + z3[g];
    }
    __syncthreads();
    {
        const int w = tid >> 5, l = tid & 31;
        const float* q = &sQ[w * 133];
        const float* k0p = &sK[l * 133];
        const float* k1p = &sK[(l + 32) * 133];
        const float* k2p = &sK[(l + 64) * 133];
        const float* k3p = (l < 4) ? &sK[(l + 96) * 133] : k0p;
        float a0 = 0.f, a1 = 0.f, a2 = 0.f, a3 = 0.f;
#pragma unroll 4
        for (int c = 0; c < 128; c++) {
            float qv = q[c];
            a0 += qv * k0p[c];
            a1 += qv * k1p[c];
            a2 += qv * k2p[c];
            a3 += qv * k3p[c];
        }
        a0 *= 0.1f; a1 *= 0.1f; a2 *= 0.1f;
        a3 = (l < 4) ? a3 * 0.1f : -1e30f;
        float mx = fmaxf(fmaxf(a0, a1), fmaxf(a2, a3));
#pragma unroll
        for (int o = 16; o; o >>= 1) mx = fmaxf(mx, __shfl_xor_sync(0xffffffffu, mx, o));
        float e0 = expf(a0 - mx), e1 = expf(a1 - mx), e2 = expf(a2 - mx);
        float e3 = (l < 4) ? expf(a3 - mx) : 0.f;
        float s = e0 + e1 + e2 + e3;
#pragma unroll
        for (int o = 16; o; o >>= 1) s += __shfl_xor_sync(0xffffffffu, s, o);
        float inv = 1.f / s;
        sP[w * 100 + l] = e0 * inv;
        sP[w * 100 + l + 32] = e1 * inv;
        sP[w * 100 + l + 64] = e2 * inv;
        if (l < 4) sP[w * 100 + l + 96] = e3 * inv;
    }
    __syncthreads();
    if (tid < 256) {
        const int c = tid;
        float acc[10];
#pragma unroll
        for (int i = 0; i < 10; i++) acc[i] = 0.f;
        for (int m = 0; m < 100; m++) {
            int g = m * 2048 + 1024 + h * 256 + c;
            float vv = z0[g] + z1[g] + z2[g] + z3[g];
            float p0 = sP[m], p1 = sP[100 + m], p2 = sP[200 + m], p3 = sP[300 + m];
            float p4 = sP[400 + m], p5 = sP[500 + m], p6 = sP[600 + m], p7 = sP[700 + m];
            float p8 = sP[800 + m], p9 = sP[900 + m];
            acc[0] += p0 * vv; acc[1] += p1 * vv; acc[2] += p2 * vv; acc[3] += p3 * vv;
            acc[4] += p4 * vv; acc[5] += p5 * vv; acc[6] += p6 * vv; acc[7] += p7 * vv;
            acc[8] += p8 * vv; acc[9] += p9 * vv;
        }
#pragma unroll
        for (int i = 0; i < 10; i++) O[(n0 + i) * 1024 + h * 256 + c] = acc[i];
    }
}

// ---------------- host launcher ----------------
extern "C" void kernel_launch(void* const* d_in, const int* in_sizes, int n_in,
                              void* d_out, int out_size) {
    const float* x = (const float*)d_in[0];
    const float* cw[10];
    const float* cb[10];
    for (int i = 0; i < 10; i++) {
        cw[i] = (const float*)d_in[1 + 2 * i];
        cb[i] = (const float*)d_in[2 + 2 * i];
    }
    const float* Wq = (const float*)d_in[21];
    const float* Wk = (const float*)d_in[22];
    const float* Wv = (const float*)d_in[23];
    const float* Wo = (const float*)d_in[24];
    const float* W1 = (const float*)d_in[25];
    const float* b1 = (const float*)d_in[26];
    const float* W2 = (const float*)d_in[27];
    const float* b2 = (const float*)d_in[28];
    float* h = (float*)d_out;

    float *bufA, *bufB, *zp, *o, *t, *tp, *part;
    cudaGetSymbolAddress((void**)&bufA, g_bufA);
    cudaGetSymbolAddress((void**)&bufB, g_bufB);
    cudaGetSymbolAddress((void**)&zp, g_zp);
    cudaGetSymbolAddress((void**)&o, g_o);
    cudaGetSymbolAddress((void**)&t, g_t);
    cudaGetSymbolAddress((void**)&tp, g_tp);
    cudaGetSymbolAddress((void**)&part, g_part);

    const int ATTN_SMEM = (100 * 133 + 10 * 133 + 10 * 100) * 4;
    cudaFuncSetAttribute(attn2, cudaFuncAttributeMaxDynamicSharedMemorySize, ATTN_SMEM);

    // ---- conv stack ----
    conv1_kernel<<<100, 256>>>(x, cw[0], cb[0], bufA);
    conv_blk<8, 8, 16, 8, 18, 2, 8, true, 128><<<dim3(100, 2), 128>>>(bufA, cw[1], cb[1], bufB);
    conv_blk<16, 16, 32, 16, 16, 4, 7, false, 112><<<dim3(100, 2), 112>>>(bufB, cw[2], cb[2], bufA);
    conv_blk<32, 16, 32, 16, 14, 4, 6, true, 96><<<dim3(100, 2), 96>>>(bufA, cw[3], cb[3], bufB);
    conv_blk<32, 16, 64, 32, 12, 4, 5, true, 160><<<dim3(100, 2), 160>>>(bufB, cw[4], cb[4], bufA);
    conv_blk<64, 16, 64, 32, 10, 4, 4, true, 128><<<dim3(100, 2), 128>>>(bufA, cw[5], cb[5], bufB);
    conv_blk<64, 8, 128, 64, 8, 4, 3, true, 192><<<dim3(100, 2), 192>>>(bufB, cw[6], cb[6], bufA);
    conv_blk<128, 8, 128, 64, 6, 4, 2, true, 128><<<dim3(100, 2), 128>>>(bufA, cw[7], cb[7], bufB);
    conv_blk<128, 8, 256, 128, 4, 4, 1, true, 128><<<dim3(100, 2), 128>>>(bufB, cw[8], cb[8], bufA);
    gemmT_loc<<<dim3(16, 2), 128>>>(bufA, cw[9], cb[9], h);

    // ---- 12 encoder layers (5 launches each, tf32 tensor-core GEMMs) ----
    for (int l = 0; l < 12; l++) {
        const float* wq = Wq + (size_t)l * 4 * 512 * 128;
        const float* wk = Wk + (size_t)l * 4 * 512 * 128;
        const float* wv = Wv + (size_t)l * 4 * 512 * 256;
        const float* wo = Wo + (size_t)l * 1024 * 512;
        const float* w1 = W1 + (size_t)l * 512 * 2048;
        const float* bb1 = b1 + (size_t)l * 2048;
        const float* w2 = W2 + (size_t)l * 2048 * 512;
        const float* bb2 = b2 + (size_t)l * 512;

        // zp[z] = h @ [Wq|Wk|Wv] partials   (split-K=4 -> 512 blocks)
        qkvP<<<dim3(64, 2, 4), 128>>>(h, wq, wk, wv, zp, 128);
        // attention folds the 4 partials internally
        attn2<<<dim3(10, 4), 320, ATTN_SMEM>>>(zp, o);
        // h += O @ Wo   (split-K=8, fused reduce)
        gemmR<0><<<dim3(16, 2, 8), 128>>>(o, wo, nullptr, part, h,
                                          100, 1024, 512, 512, 512, 128, 8, 16);
        // t = relu(h @ W1 + b1)   (split-K=4, fused reduce)
        gemmR<1><<<dim3(64, 2, 4), 128>>>(h, w1, bb1, tp, t,
                                          100, 512, 2048, 2048, 2048, 128, 4, 64);
        // h += t @ W2 + b2   (split-K=8, fused reduce)
        gemmR<2><<<dim3(16, 2, 8), 128>>>(t, w2, bb2, part, h,
                                          100, 2048, 512, 512, 512, 256, 8, 16);
    }
}

// round 14
// speedup vs baseline: 1.8117x; 1.0964x over previous
#include <cuda_runtime.h>
#include <stdint.h>
#include <math.h>

// ---------------- scratch ----------------
__device__ __align__(16) float g_bufA[100 * 6400];
__device__ __align__(16) float g_bufB[100 * 4608];
__device__ __align__(16) float g_zp[4 * 100 * 2048];   // qkv / W1 split-K partials
__device__ __align__(16) float g_z[100 * 2048];        // folded QKV
__device__ __align__(16) float g_o[100 * 1024];        // attention out
__device__ __align__(16) float g_t[100 * 2048];        // FFN hidden
__device__ __align__(16) float g_part[16 * 100 * 512]; // Wo / W2 split-K partials
__device__ int g_cnt[128];    // split-K tile counters (self-resetting)
__device__ int g_barCnt;      // grid barrier arrivals
__device__ int g_barSense;    // grid barrier phase (monotone)

__device__ __forceinline__ float4 ld4(const float* p) { return *(const float4*)p; }

__device__ __forceinline__ uint32_t tf32c(float x) {
    uint32_t u;
    asm("cvt.rna.tf32.f32 %0, %1;" : "=r"(u) : "f"(x));
    return u;
}
__device__ __forceinline__ float4 tf32c4(float4 v) {
    return make_float4(__uint_as_float(tf32c(v.x)), __uint_as_float(tf32c(v.y)),
                       __uint_as_float(tf32c(v.z)), __uint_as_float(tf32c(v.w)));
}
__device__ __forceinline__ void mma_tf32(float* c, uint32_t a0, uint32_t a1, uint32_t a2,
                                         uint32_t a3, uint32_t b0, uint32_t b1) {
    asm volatile(
        "mma.sync.aligned.m16n8k8.row.col.f32.tf32.tf32.f32 "
        "{%0,%1,%2,%3}, {%4,%5,%6,%7}, {%8,%9}, {%0,%1,%2,%3};"
        : "+f"(c[0]), "+f"(c[1]), "+f"(c[2]), "+f"(c[3])
        : "r"(a0), "r"(a1), "r"(a2), "r"(a3), "r"(b0), "r"(b1));
}

// ---------------- conv1 ----------------
__global__ void conv1_kernel(const float* __restrict__ x, const float* __restrict__ w,
                             const float* __restrict__ b, float* __restrict__ out) {
    __shared__ float s_in[1200];
    __shared__ float s_w[216];
    __shared__ float s_b[8];
    const int p = blockIdx.x;
    const int r0 = 20 * (p % 10), c0 = 20 * (p / 10);
    for (int idx = threadIdx.x; idx < 1200; idx += blockDim.x) {
        int c = idx / 400, rem = idx % 400, y = rem / 20, xx = rem % 20;
        s_in[idx] = x[c * 40000 + (r0 + y) * 200 + c0 + xx];
    }
    for (int idx = threadIdx.x; idx < 216; idx += blockDim.x) s_w[idx] = w[idx];
    if (threadIdx.x < 8) s_b[threadIdx.x] = b[threadIdx.x];
    __syncthreads();
    for (int idx = threadIdx.x; idx < 8 * 324; idx += blockDim.x) {
        int oc = idx / 324, rem = idx % 324, oy = rem / 18, ox = rem % 18;
        float acc = s_b[oc];
        const float* wp = s_w + oc * 27;
#pragma unroll
        for (int ci = 0; ci < 3; ci++)
#pragma unroll
            for (int ky = 0; ky < 3; ky++)
#pragma unroll
                for (int kx = 0; kx < 3; kx++)
                    acc += s_in[ci * 400 + (oy + ky) * 20 + ox + kx] * wp[ci * 9 + ky * 3 + kx];
        out[p * 2592 + idx] = acc;
    }
}

// ---------------- conv_blk (unchanged) ----------------
template <int CI, int CIB, int CO, int OCB, int SIN, int OCT, int CHUNK, bool RELU, int NT>
__global__ __launch_bounds__(NT) void conv_blk(const float* __restrict__ in,
                                               const float* __restrict__ w,
                                               const float* __restrict__ bias,
                                               float* __restrict__ out) {
    constexpr int SOUT = SIN - 2;
    constexpr int SP = SOUT * SOUT;
    constexpr int SS = SIN * SIN;
    constexpr int NSP = SP / CHUNK;
    constexpr int NOC = OCB / OCT;
    static_assert(NOC * NSP == NT, "thread count mismatch");
    static_assert(NSP * CHUNK == SP, "chunk mismatch");
    __shared__ __align__(16) float s_in[CI * SS];
    __shared__ __align__(16) float s_w[OCB * CIB * 9];
    const int p = blockIdx.x;
    const int ocb0 = blockIdx.y * OCB;
    const float* inp = in + (size_t)p * CI * SS;
    for (int i = threadIdx.x; i < CI * SS / 4; i += NT)
        ((float4*)s_in)[i] = ((const float4*)inp)[i];
    const int ocg = threadIdx.x / NSP;
    const int spg = threadIdx.x % NSP;
    const int oc0 = ocg * OCT, sp0 = spg * CHUNK;
    int off[CHUNK];
#pragma unroll
    for (int u = 0; u < CHUNK; u++) {
        int pos = sp0 + u;
        off[u] = (pos / SOUT) * SIN + (pos % SOUT);
    }
    float acc[OCT][CHUNK] = {};
#pragma unroll 1
    for (int cb = 0; cb < CI / CIB; cb++) {
        __syncthreads();
        for (int i = threadIdx.x; i < OCB * CIB * 9 / 4; i += NT) {
            int flat = i * 4;
            int oc = flat / (CIB * 9), r = flat % (CIB * 9);
            ((float4*)s_w)[i] = ld4(w + (size_t)(ocb0 + oc) * CI * 9 + cb * CIB * 9 + r);
        }
        __syncthreads();
#pragma unroll
        for (int ci = 0; ci < CIB; ci++) {
            const float* ib = s_in + (cb * CIB + ci) * SS;
            const float* wb = s_w + oc0 * (CIB * 9) + ci * 9;
#pragma unroll
            for (int k = 0; k < 9; k++) {
                const int ky = k / 3, kx = k % 3;
                float wf[OCT];
#pragma unroll
                for (int o = 0; o < OCT; o++) wf[o] = wb[o * (CIB * 9) + k];
                float xf[CHUNK];
                const float* ip = ib + ky * SIN + kx;
#pragma unroll
                for (int u = 0; u < CHUNK; u++) xf[u] = ip[off[u]];
#pragma unroll
                for (int o = 0; o < OCT; o++)
#pragma unroll
                    for (int u = 0; u < CHUNK; u++) acc[o][u] += wf[o] * xf[u];
            }
        }
    }
#pragma unroll
    for (int o = 0; o < OCT; o++) {
        float bv = bias[ocb0 + oc0 + o];
#pragma unroll
        for (int u = 0; u < CHUNK; u++) {
            float r = acc[o][u] + bv;
            if (RELU) r = fmaxf(r, 0.f);
            out[(size_t)p * CO * SP + (ocb0 + oc0 + o) * SP + sp0 + u] = r;
        }
    }
}

// ---------------- gemmT_loc (conv10 + location embedding, fp32, runs once) ----------------
__global__ __launch_bounds__(128) void gemmT_loc(const float* __restrict__ A,
                                                 const float* __restrict__ W,
                                                 const float* __restrict__ bias,
                                                 float* __restrict__ C) {
    const int M = 100;
    __shared__ __align__(16) float As[16][64];
    __shared__ __align__(16) float Bs[16][32];
    const int t = threadIdx.x;
    const int ty = t >> 3, tx = t & 7;
    const int am = t >> 2, ak4 = (t & 3) << 2;
    const int bn = t & 31, k4 = ((t >> 5) & 3) << 2;
    const int m0 = blockIdx.y * 64, n0 = blockIdx.x * 32;
    float acc[4][4] = {};
    for (int kk0 = 0; kk0 < 1024; kk0 += 16) {
        float4 a0 = make_float4(0.f, 0.f, 0.f, 0.f), a1 = a0;
        if (m0 + am < M) a0 = ld4(A + (long long)(m0 + am) * 1024 + kk0 + ak4);
        if (m0 + am + 32 < M) a1 = ld4(A + (long long)(m0 + am + 32) * 1024 + kk0 + ak4);
        As[ak4 + 0][am] = a0.x; As[ak4 + 1][am] = a0.y;
        As[ak4 + 2][am] = a0.z; As[ak4 + 3][am] = a0.w;
        As[ak4 + 0][am + 32] = a1.x; As[ak4 + 1][am + 32] = a1.y;
        As[ak4 + 2][am + 32] = a1.z; As[ak4 + 3][am + 32] = a1.w;
        float4 wv = ld4(W + (long long)(n0 + bn) * 1024 + kk0 + k4);
        Bs[k4 + 0][bn] = wv.x; Bs[k4 + 1][bn] = wv.y;
        Bs[k4 + 2][bn] = wv.z; Bs[k4 + 3][bn] = wv.w;
        __syncthreads();
#pragma unroll
        for (int kk = 0; kk < 16; kk++) {
            float4 a4 = *(const float4*)(&As[kk][ty << 2]);
            float4 b4 = *(const float4*)(&Bs[kk][tx << 2]);
            acc[0][0] += a4.x * b4.x; acc[0][1] += a4.x * b4.y; acc[0][2] += a4.x * b4.z; acc[0][3] += a4.x * b4.w;
            acc[1][0] += a4.y * b4.x; acc[1][1] += a4.y * b4.y; acc[1][2] += a4.y * b4.z; acc[1][3] += a4.y * b4.w;
            acc[2][0] += a4.z * b4.x; acc[2][1] += a4.z * b4.y; acc[2][2] += a4.z * b4.z; acc[2][3] += a4.z * b4.w;
            acc[3][0] += a4.w * b4.x; acc[3][1] += a4.w * b4.y; acc[3][2] += a4.w * b4.z; acc[3][3] += a4.w * b4.w;
        }
        __syncthreads();
    }
#pragma unroll
    for (int i = 0; i < 4; i++) {
        int m = m0 + (ty << 2) + i;
        if (m >= M) break;
        float pos = 20.f * (float)(m / 10);
#pragma unroll
        for (int j = 0; j < 4; j++) {
            int n = n0 + (tx << 2) + j;
            float v = acc[i][j] + bias[n];
            int kkn = (n < 256) ? n : n - 256;
            float inv = exp2f(-(2.f * (float)kkn / 256.f) * 13.287712379549449f);
            float ang = pos * inv;
            v += (n < 256) ? sinf(ang) : cosf(ang);
            C[(long long)m * 512 + n] = v;
        }
    }
}

// ---------------- tf32 MMA GEMM core (unchanged) ----------------
struct MmaSmem {
    float As[2][64][36];
    float Bs[2][32][36];
};

#define MMA_STAGE(BUF, AA0, AA1, AA2, AA3, BB0, BB1)                                     \
    {                                                                                    \
        float4 c0 = tf32c4(AA0), c1 = tf32c4(AA1), c2 = tf32c4(AA2), c3 = tf32c4(AA3);   \
        *(float4*)&S->As[BUF][am][ac] = c0;                                              \
        *(float4*)&S->As[BUF][am][ac + 4] = c1;                                          \
        *(float4*)&S->As[BUF][am + 32][ac] = c2;                                         \
        *(float4*)&S->As[BUF][am + 32][ac + 4] = c3;                                     \
        *(float4*)&S->Bs[BUF][bk][bc] = tf32c4(BB0);                                     \
        *(float4*)&S->Bs[BUF][bk][bc + 4] = tf32c4(BB1);                                 \
    }

#define MMA_COMPUTE(BUF)                                                                 \
    _Pragma("unroll") for (int ks = 0; ks < 4; ks++) {                                   \
        const int kb = ks * 8;                                                           \
        uint32_t a0 = __float_as_uint(S->As[BUF][w16 + g][kb + tig]);                    \
        uint32_t a1 = __float_as_uint(S->As[BUF][w16 + g + 8][kb + tig]);                \
        uint32_t a2 = __float_as_uint(S->As[BUF][w16 + g][kb + tig + 4]);                \
        uint32_t a3 = __float_as_uint(S->As[BUF][w16 + g + 8][kb + tig + 4]);            \
        _Pragma("unroll") for (int nb = 0; nb < 4; nb++) {                               \
            uint32_t b0 = __float_as_uint(S->Bs[BUF][kb + tig][nb * 8 + g]);             \
            uint32_t b1 = __float_as_uint(S->Bs[BUF][kb + tig + 4][nb * 8 + g]);         \
            mma_tf32(acc[nb], a0, a1, a2, a3, b0, b1);                                   \
        }                                                                                \
    }

__device__ __forceinline__ void gemm_mma(const float* A0, const float* A1, bool v0, bool v1,
                                         const float* Bb, int ldb, int k0, int nIter,
                                         MmaSmem* S, float (&acc)[4][4]) {
    const int t = threadIdx.x;
    const int am = t >> 2, ac = (t & 3) << 3;
    const int bk = t >> 2, bc = (t & 3) << 3;
    const int w16 = (t >> 5) << 4;
    const int g = (t & 31) >> 2, tig = t & 3;
    const float4 z4 = make_float4(0.f, 0.f, 0.f, 0.f);
    {
        float4 a0 = v0 ? ld4(A0 + k0) : z4, a1 = v0 ? ld4(A0 + k0 + 4) : z4;
        float4 a2 = v1 ? ld4(A1 + k0) : z4, a3 = v1 ? ld4(A1 + k0 + 4) : z4;
        float4 b0 = ld4(Bb + (long long)k0 * ldb);
        float4 b1 = ld4(Bb + (long long)k0 * ldb + 4);
        MMA_STAGE(0, a0, a1, a2, a3, b0, b1)
    }
    __syncthreads();
    int buf = 0;
    for (int it = 0; it < nIter; ++it) {
        float4 a0, a1, a2, a3, b0, b1;
        const bool pf = (it + 1) < nIter;
        if (pf) {
            const int kn = k0 + ((it + 1) << 5);
            a0 = v0 ? ld4(A0 + kn) : z4; a1 = v0 ? ld4(A0 + kn + 4) : z4;
            a2 = v1 ? ld4(A1 + kn) : z4; a3 = v1 ? ld4(A1 + kn + 4) : z4;
            b0 = ld4(Bb + (long long)kn * ldb);
            b1 = ld4(Bb + (long long)kn * ldb + 4);
        }
        MMA_COMPUTE(buf)
        if (pf) {
            const int nb2 = buf ^ 1;
            __syncthreads();
            MMA_STAGE(nb2, a0, a1, a2, a3, b0, b1)
            __syncthreads();
            buf = nb2;
        }
    }
}

// ---------------- split-K GEMM stage with counter-fused deterministic reduce ----------------
// EPI 0: out += sum   1: out = relu(sum+bias)   2: out += sum+bias   3: out = sum
template <int EPI>
__device__ __forceinline__ void gemm_splitk(const float* A, int lda, const float* B, int ldb,
                                            int n0B, float* part, float* out,
                                            const float* bias, int N, int ldOut, int m0,
                                            int n0, int k0, int kPerZ, int z, int Z,
                                            int tileId, char* sraw, int* s_last) {
    MmaSmem* S = (MmaSmem*)sraw;
    const int t = threadIdx.x;
    const int am = t >> 2, ac = (t & 3) << 3;
    const int bc = (t & 3) << 3;
    const int w16 = (t >> 5) << 4;
    const int g = (t & 31) >> 2, tig = t & 3;
    const bool v0 = (m0 + am) < 100, v1 = (m0 + am + 32) < 100;
    const float* A0 = A + (long long)(m0 + am) * lda + ac;
    const float* A1 = A + (long long)(m0 + am + 32) * lda + ac;
    const float* Bb = B + (long long)(t >> 2) * ldb + n0B + bc;
    float acc[4][4] = {};
    gemm_mma(A0, A1, v0, v1, Bb, ldb, k0, kPerZ >> 5, S, acc);

    float* pp = part + (long long)z * 100 * N;
    const int r0 = m0 + w16 + g, r1 = r0 + 8;
#pragma unroll
    for (int nb = 0; nb < 4; nb++) {
        const int col = n0 + nb * 8 + tig * 2;
        if (r0 < 100) *(float2*)(pp + (long long)r0 * N + col) = make_float2(acc[nb][0], acc[nb][1]);
        if (r1 < 100) *(float2*)(pp + (long long)r1 * N + col) = make_float2(acc[nb][2], acc[nb][3]);
    }
    __threadfence();
    __syncthreads();
    if (t == 0) {
        int old = atomicAdd(&g_cnt[tileId], 1);
        *s_last = (old == Z - 1) ? 1 : 0;
    }
    __syncthreads();
    if (*s_last) {
        __threadfence();
#pragma unroll
        for (int nb = 0; nb < 4; nb++) {
            const int col = n0 + nb * 8 + tig * 2;
#pragma unroll
            for (int half = 0; half < 2; half++) {
                const int m = half ? r1 : r0;
                if (m >= 100) continue;
                float2 s2 = make_float2(0.f, 0.f);
                for (int zz = 0; zz < Z; zz++) {
                    float2 v = __ldcg((const float2*)(part + (long long)zz * 100 * N +
                                                      (long long)m * N + col));
                    s2.x += v.x; s2.y += v.y;
                }
                float* op = out + (long long)m * ldOut + col;
                if (EPI == 0) {
                    op[0] += s2.x; op[1] += s2.y;
                } else if (EPI == 1) {
                    float2 b2 = *(const float2*)(bias + col);
                    op[0] = fmaxf(s2.x + b2.x, 0.f);
                    op[1] = fmaxf(s2.y + b2.y, 0.f);
                } else if (EPI == 2) {
                    float2 b2 = *(const float2*)(bias + col);
                    op[0] += s2.x + b2.x;
                    op[1] += s2.y + b2.y;
                } else {
                    op[0] = s2.x; op[1] = s2.y;
                }
            }
        }
        __syncthreads();
        if (t == 0) g_cnt[tileId] = 0;
    }
}

// ---------------- attention unit: one (query n, head h) per 128-thread block ----------------
__device__ __forceinline__ void attn_unit(const float* __restrict__ z, float* __restrict__ O,
                                          int n, int h, char* sraw) {
    float* sq = (float*)sraw;    // 128
    float* sa = sq + 128;        // 104
    float* red = sa + 104;       // 4
    const int tid = threadIdx.x;
    sq[tid] = z[n * 2048 + h * 128 + tid];
    __syncthreads();
    float s = -1e30f;
    if (tid < 100) {
        const float* kr = z + tid * 2048 + 512 + h * 128;
        float a = 0.f;
#pragma unroll 8
        for (int i = 0; i < 128; i++) a += sq[i] * kr[i];
        s = a * 0.1f;
    }
    float v = s;
#pragma unroll
    for (int o2 = 16; o2; o2 >>= 1) v = fmaxf(v, __shfl_xor_sync(0xffffffffu, v, o2));
    if ((tid & 31) == 0) red[tid >> 5] = v;
    __syncthreads();
    float mx = fmaxf(fmaxf(red[0], red[1]), fmaxf(red[2], red[3]));
    float e = (tid < 100) ? expf(s - mx) : 0.f;
    float sv = e;
#pragma unroll
    for (int o2 = 16; o2; o2 >>= 1) sv += __shfl_xor_sync(0xffffffffu, sv, o2);
    __syncthreads();
    if ((tid & 31) == 0) red[tid >> 5] = sv;
    __syncthreads();
    float sum = red[0] + red[1] + red[2] + red[3];
    if (tid < 100) sa[tid] = e / sum;
    __syncthreads();
#pragma unroll
    for (int pass = 0; pass < 2; pass++) {
        const int c = tid + pass * 128;
        const float* vb = z + 1024 + h * 256 + c;
        float a0 = 0.f, a1 = 0.f, a2 = 0.f, a3 = 0.f;
        for (int m = 0; m < 100; m += 4) {
            a0 += sa[m] * vb[(long long)m * 2048];
            a1 += sa[m + 1] * vb[(long long)(m + 1) * 2048];
            a2 += sa[m + 2] * vb[(long long)(m + 2) * 2048];
            a3 += sa[m + 3] * vb[(long long)(m + 3) * 2048];
        }
        O[n * 1024 + h * 256 + c] = (a0 + a1) + (a2 + a3);
    }
    __syncthreads();
}

// ---------------- grid barrier (sense-forward, co-resident grid, bounded spin) ----------------
__device__ __forceinline__ void gbar(int& phase) {
    __syncthreads();
    if (threadIdx.x == 0) {
        __threadfence();
        int a = atomicAdd(&g_barCnt, 1);
        if (a == 511) {
            g_barCnt = 0;
            __threadfence();
            atomicExch(&g_barSense, phase + 1);
        } else {
            int it = 0;
            while (*((volatile int*)&g_barSense) <= phase && it < (1 << 25)) {
                __nanosleep(32);
                ++it;
            }
            __threadfence();
        }
    }
    __syncthreads();
    phase++;
}

// ---------------- persistent encoder: all 12 layers, one launch ----------------
__global__ __launch_bounds__(128, 4) void encoder_kernel(
    float* __restrict__ h, const float* __restrict__ Wq, const float* __restrict__ Wk,
    const float* __restrict__ Wv, const float* __restrict__ Wo,
    const float* __restrict__ W1, const float* __restrict__ b1,
    const float* __restrict__ W2, const float* __restrict__ b2) {
    __shared__ __align__(16) char sraw[sizeof(MmaSmem)];
    __shared__ int s_last;
    __shared__ int s_ph;
    const int b = blockIdx.x;
    if (threadIdx.x == 0) s_ph = *((volatile int*)&g_barSense);
    __syncthreads();
    int phase = s_ph;

    for (int l = 0; l < 12; l++) {
        const float* wq = Wq + (size_t)l * 262144;
        const float* wk = Wk + (size_t)l * 262144;
        const float* wv = Wv + (size_t)l * 524288;
        const float* wo = Wo + (size_t)l * 524288;
        const float* w1 = W1 + (size_t)l * 1048576;
        const float* bb1 = b1 + (size_t)l * 2048;
        const float* w2 = W2 + (size_t)l * 1048576;
        const float* bb2 = b2 + (size_t)l * 512;

        {  // stage 1: z = h @ [Wq|Wk|Wv]  (512 tiles = 64n x 2m x 4z, fold fused)
            const int zz = b & 3, mt = (b >> 2) & 1, nt = b >> 3;
            const int n0 = nt * 32, m0 = mt * 64, k0 = zz * 128;
            const float* Bp; int ldb, n0B;
            if (n0 < 512)       { Bp = wq + (n0 >> 7) * 65536; n0B = n0 & 127; ldb = 128; }
            else if (n0 < 1024) { int c = n0 - 512;  Bp = wk + (c >> 7) * 65536; n0B = c & 127; ldb = 128; }
            else                { int c = n0 - 1024; Bp = wv + (c >> 8) * 131072; n0B = c & 255; ldb = 256; }
            gemm_splitk<3>(h, 512, Bp, ldb, n0B, g_zp, g_z, nullptr, 2048, 2048,
                           m0, n0, k0, 128, zz, 4, nt * 2 + mt, sraw, &s_last);
        }
        gbar(phase);
        if (b < 400) attn_unit(g_z, g_o, b >> 2, b & 3, sraw);   // stage 2
        gbar(phase);
        {  // stage 3: h += O @ Wo  (512 tiles = 16n x 2m x 16z)
            const int zz = b & 15, mt = (b >> 4) & 1, nt = b >> 5;
            gemm_splitk<0>(g_o, 1024, wo, 512, nt * 32, g_part, h, nullptr, 512, 512,
                           mt * 64, nt * 32, zz * 64, 64, zz, 16, nt * 2 + mt, sraw, &s_last);
        }
        gbar(phase);
        {  // stage 4: t = relu(h @ W1 + b1)  (512 tiles = 64n x 2m x 4z)
            const int zz = b & 3, mt = (b >> 2) & 1, nt = b >> 3;
            gemm_splitk<1>(h, 512, w1, 2048, nt * 32, g_zp, g_t, bb1, 2048, 2048,
                           mt * 64, nt * 32, zz * 128, 128, zz, 4, nt * 2 + mt, sraw, &s_last);
        }
        gbar(phase);
        {  // stage 5: h += t @ W2 + b2  (512 tiles = 16n x 2m x 16z)
            const int zz = b & 15, mt = (b >> 4) & 1, nt = b >> 5;
            gemm_splitk<2>(g_t, 2048, w2, 512, nt * 32, g_part, h, bb2, 512, 512,
                           mt * 64, nt * 32, zz * 128, 128, zz, 16, nt * 2 + mt, sraw, &s_last);
        }
        gbar(phase);
    }
}

// ---------------- host launcher ----------------
extern "C" void kernel_launch(void* const* d_in, const int* in_sizes, int n_in,
                              void* d_out, int out_size) {
    const float* x = (const float*)d_in[0];
    const float* cw[10];
    const float* cb[10];
    for (int i = 0; i < 10; i++) {
        cw[i] = (const float*)d_in[1 + 2 * i];
        cb[i] = (const float*)d_in[2 + 2 * i];
    }
    const float* Wq = (const float*)d_in[21];
    const float* Wk = (const float*)d_in[22];
    const float* Wv = (const float*)d_in[23];
    const float* Wo = (const float*)d_in[24];
    const float* W1 = (const float*)d_in[25];
    const float* b1 = (const float*)d_in[26];
    const float* W2 = (const float*)d_in[27];
    const float* b2 = (const float*)d_in[28];
    float* h = (float*)d_out;

    float *bufA, *bufB;
    cudaGetSymbolAddress((void**)&bufA, g_bufA);
    cudaGetSymbolAddress((void**)&bufB, g_bufB);

    // ---- conv stack ----
    conv1_kernel<<<100, 256>>>(x, cw[0], cb[0], bufA);
    conv_blk<8, 8, 16, 8, 18, 2, 8, true, 128><<<dim3(100, 2), 128>>>(bufA, cw[1], cb[1], bufB);
    conv_blk<16, 16, 32, 16, 16, 4, 7, false, 112><<<dim3(100, 2), 112>>>(bufB, cw[2], cb[2], bufA);
    conv_blk<32, 16, 32, 16, 14, 4, 6, true, 96><<<dim3(100, 2), 96>>>(bufA, cw[3], cb[3], bufB);
    conv_blk<32, 16, 64, 32, 12, 4, 5, true, 160><<<dim3(100, 2), 160>>>(bufB, cw[4], cb[4], bufA);
    conv_blk<64, 16, 64, 32, 10, 4, 4, true, 128><<<dim3(100, 2), 128>>>(bufA, cw[5], cb[5], bufB);
    conv_blk<64, 8, 128, 64, 8, 4, 3, true, 192><<<dim3(100, 2), 192>>>(bufB, cw[6], cb[6], bufA);
    conv_blk<128, 8, 128, 64, 6, 4, 2, true, 128><<<dim3(100, 2), 128>>>(bufA, cw[7], cb[7], bufB);
    conv_blk<128, 8, 256, 128, 4, 4, 1, true, 128><<<dim3(100, 2), 128>>>(bufB, cw[8], cb[8], bufA);
    gemmT_loc<<<dim3(16, 2), 128>>>(bufA, cw[9], cb[9], h);

    // ---- all 12 encoder layers in one persistent launch ----
    encoder_kernel<<<512, 128>>>(h, Wq, Wk, Wv, Wo, W1, b1, W2, b2);
}

// round 15
// speedup vs baseline: 1.8936x; 1.0452x over previous
#include <cuda_runtime.h>
#include <stdint.h>
#include <math.h>

// ---------------- scratch ----------------
__device__ __align__(16) float g_bufA[100 * 6400];
__device__ __align__(16) float g_bufB[100 * 4608];
__device__ __align__(16) float g_zp[4 * 100 * 2048];   // qkv / W1 split-K partials
__device__ __align__(16) float g_z[100 * 2048];        // folded QKV
__device__ __align__(16) float g_o[100 * 1024];        // attention out
__device__ __align__(16) float g_t[100 * 2048];        // FFN hidden
__device__ __align__(16) float g_part[16 * 100 * 512]; // Wo / W2 split-K partials
__device__ int g_cnt[128];    // split-K tile counters (self-resetting)
__device__ int g_barCnt;      // grid barrier arrivals
__device__ int g_barSense;    // grid barrier phase (monotone)

__device__ __forceinline__ float4 ld4(const float* p) { return *(const float4*)p; }

__device__ __forceinline__ uint32_t tf32c(float x) {
    uint32_t u;
    asm("cvt.rna.tf32.f32 %0, %1;" : "=r"(u) : "f"(x));
    return u;
}
__device__ __forceinline__ float4 tf32c4(float4 v) {
    return make_float4(__uint_as_float(tf32c(v.x)), __uint_as_float(tf32c(v.y)),
                       __uint_as_float(tf32c(v.z)), __uint_as_float(tf32c(v.w)));
}
__device__ __forceinline__ void mma_tf32(float* c, uint32_t a0, uint32_t a1, uint32_t a2,
                                         uint32_t a3, uint32_t b0, uint32_t b1) {
    asm volatile(
        "mma.sync.aligned.m16n8k8.row.col.f32.tf32.tf32.f32 "
        "{%0,%1,%2,%3}, {%4,%5,%6,%7}, {%8,%9}, {%0,%1,%2,%3};"
        : "+f"(c[0]), "+f"(c[1]), "+f"(c[2]), "+f"(c[3])
        : "r"(a0), "r"(a1), "r"(a2), "r"(a3), "r"(b0), "r"(b1));
}

// ---------------- conv1 ----------------
__global__ void conv1_kernel(const float* __restrict__ x, const float* __restrict__ w,
                             const float* __restrict__ b, float* __restrict__ out) {
    __shared__ float s_in[1200];
    __shared__ float s_w[216];
    __shared__ float s_b[8];
    const int p = blockIdx.x;
    const int r0 = 20 * (p % 10), c0 = 20 * (p / 10);
    for (int idx = threadIdx.x; idx < 1200; idx += blockDim.x) {
        int c = idx / 400, rem = idx % 400, y = rem / 20, xx = rem % 20;
        s_in[idx] = x[c * 40000 + (r0 + y) * 200 + c0 + xx];
    }
    for (int idx = threadIdx.x; idx < 216; idx += blockDim.x) s_w[idx] = w[idx];
    if (threadIdx.x < 8) s_b[threadIdx.x] = b[threadIdx.x];
    __syncthreads();
    for (int idx = threadIdx.x; idx < 8 * 324; idx += blockDim.x) {
        int oc = idx / 324, rem = idx % 324, oy = rem / 18, ox = rem % 18;
        float acc = s_b[oc];
        const float* wp = s_w + oc * 27;
#pragma unroll
        for (int ci = 0; ci < 3; ci++)
#pragma unroll
            for (int ky = 0; ky < 3; ky++)
#pragma unroll
                for (int kx = 0; kx < 3; kx++)
                    acc += s_in[ci * 400 + (oy + ky) * 20 + ox + kx] * wp[ci * 9 + ky * 3 + kx];
        out[p * 2592 + idx] = acc;
    }
}

// ---------------- conv_blk ----------------
template <int CI, int CIB, int CO, int OCB, int SIN, int OCT, int CHUNK, bool RELU, int NT>
__global__ __launch_bounds__(NT) void conv_blk(const float* __restrict__ in,
                                               const float* __restrict__ w,
                                               const float* __restrict__ bias,
                                               float* __restrict__ out) {
    constexpr int SOUT = SIN - 2;
    constexpr int SP = SOUT * SOUT;
    constexpr int SS = SIN * SIN;
    constexpr int NSP = SP / CHUNK;
    constexpr int NOC = OCB / OCT;
    static_assert(NOC * NSP == NT, "thread count mismatch");
    static_assert(NSP * CHUNK == SP, "chunk mismatch");
    static_assert((CI * SS) % 4 == 0 && (CIB * 9) % 4 == 0 && (CI * 9) % 4 == 0, "vec");
    __shared__ __align__(16) float s_in[CI * SS];
    __shared__ __align__(16) float s_w[OCB * CIB * 9];
    const int p = blockIdx.x;
    const int ocb0 = blockIdx.y * OCB;
    const float* inp = in + (size_t)p * CI * SS;
    for (int i = threadIdx.x; i < CI * SS / 4; i += NT)
        ((float4*)s_in)[i] = ((const float4*)inp)[i];
    const int ocg = threadIdx.x / NSP;
    const int spg = threadIdx.x % NSP;
    const int oc0 = ocg * OCT, sp0 = spg * CHUNK;
    int off[CHUNK];
#pragma unroll
    for (int u = 0; u < CHUNK; u++) {
        int pos = sp0 + u;
        off[u] = (pos / SOUT) * SIN + (pos % SOUT);
    }
    float acc[OCT][CHUNK] = {};
#pragma unroll 1
    for (int cb = 0; cb < CI / CIB; cb++) {
        __syncthreads();
        for (int i = threadIdx.x; i < OCB * CIB * 9 / 4; i += NT) {
            int flat = i * 4;
            int oc = flat / (CIB * 9), r = flat % (CIB * 9);
            ((float4*)s_w)[i] = ld4(w + (size_t)(ocb0 + oc) * CI * 9 + cb * CIB * 9 + r);
        }
        __syncthreads();
#pragma unroll
        for (int ci = 0; ci < CIB; ci++) {
            const float* ib = s_in + (cb * CIB + ci) * SS;
            const float* wb = s_w + oc0 * (CIB * 9) + ci * 9;
#pragma unroll
            for (int k = 0; k < 9; k++) {
                const int ky = k / 3, kx = k % 3;
                float wf[OCT];
#pragma unroll
                for (int o = 0; o < OCT; o++) wf[o] = wb[o * (CIB * 9) + k];
                float xf[CHUNK];
                const float* ip = ib + ky * SIN + kx;
#pragma unroll
                for (int u = 0; u < CHUNK; u++) xf[u] = ip[off[u]];
#pragma unroll
                for (int o = 0; o < OCT; o++)
#pragma unroll
                    for (int u = 0; u < CHUNK; u++) acc[o][u] += wf[o] * xf[u];
            }
        }
    }
#pragma unroll
    for (int o = 0; o < OCT; o++) {
        float bv = bias[ocb0 + oc0 + o];
#pragma unroll
        for (int u = 0; u < CHUNK; u++) {
            float r = acc[o][u] + bv;
            if (RELU) r = fmaxf(r, 0.f);
            out[(size_t)p * CO * SP + (ocb0 + oc0 + o) * SP + sp0 + u] = r;
        }
    }
}

// ---------------- gemmT_loc (conv10 + location embedding, fp32, runs once) ----------------
__global__ __launch_bounds__(128) void gemmT_loc(const float* __restrict__ A,
                                                 const float* __restrict__ W,
                                                 const float* __restrict__ bias,
                                                 float* __restrict__ C) {
    const int M = 100;
    __shared__ __align__(16) float As[16][64];
    __shared__ __align__(16) float Bs[16][32];
    const int t = threadIdx.x;
    const int ty = t >> 3, tx = t & 7;
    const int am = t >> 2, ak4 = (t & 3) << 2;
    const int bn = t & 31, k4 = ((t >> 5) & 3) << 2;
    const int m0 = blockIdx.y * 64, n0 = blockIdx.x * 32;
    float acc[4][4] = {};
    for (int kk0 = 0; kk0 < 1024; kk0 += 16) {
        float4 a0 = make_float4(0.f, 0.f, 0.f, 0.f), a1 = a0;
        if (m0 + am < M) a0 = ld4(A + (long long)(m0 + am) * 1024 + kk0 + ak4);
        if (m0 + am + 32 < M) a1 = ld4(A + (long long)(m0 + am + 32) * 1024 + kk0 + ak4);
        As[ak4 + 0][am] = a0.x; As[ak4 + 1][am] = a0.y;
        As[ak4 + 2][am] = a0.z; As[ak4 + 3][am] = a0.w;
        As[ak4 + 0][am + 32] = a1.x; As[ak4 + 1][am + 32] = a1.y;
        As[ak4 + 2][am + 32] = a1.z; As[ak4 + 3][am + 32] = a1.w;
        float4 wv = ld4(W + (long long)(n0 + bn) * 1024 + kk0 + k4);
        Bs[k4 + 0][bn] = wv.x; Bs[k4 + 1][bn] = wv.y;
        Bs[k4 + 2][bn] = wv.z; Bs[k4 + 3][bn] = wv.w;
        __syncthreads();
#pragma unroll
        for (int kk = 0; kk < 16; kk++) {
            float4 a4 = *(const float4*)(&As[kk][ty << 2]);
            float4 b4 = *(const float4*)(&Bs[kk][tx << 2]);
            acc[0][0] += a4.x * b4.x; acc[0][1] += a4.x * b4.y; acc[0][2] += a4.x * b4.z; acc[0][3] += a4.x * b4.w;
            acc[1][0] += a4.y * b4.x; acc[1][1] += a4.y * b4.y; acc[1][2] += a4.y * b4.z; acc[1][3] += a4.y * b4.w;
            acc[2][0] += a4.z * b4.x; acc[2][1] += a4.z * b4.y; acc[2][2] += a4.z * b4.z; acc[2][3] += a4.z * b4.w;
            acc[3][0] += a4.w * b4.x; acc[3][1] += a4.w * b4.y; acc[3][2] += a4.w * b4.z; acc[3][3] += a4.w * b4.w;
        }
        __syncthreads();
    }
#pragma unroll
    for (int i = 0; i < 4; i++) {
        int m = m0 + (ty << 2) + i;
        if (m >= M) break;
        float pos = 20.f * (float)(m / 10);
#pragma unroll
        for (int j = 0; j < 4; j++) {
            int n = n0 + (tx << 2) + j;
            float v = acc[i][j] + bias[n];
            int kkn = (n < 256) ? n : n - 256;
            float inv = exp2f(-(2.f * (float)kkn / 256.f) * 13.287712379549449f);
            float ang = pos * inv;
            v += (n < 256) ? sinf(ang) : cosf(ang);
            C[(long long)m * 512 + n] = v;
        }
    }
}

// ---------------- tf32 MMA GEMM core ----------------
// Bs stride 40: B compute-load banks (8*tig + g + 8*nb) % 32 -> conflict-free.
struct MmaSmem {
    float As[2][64][36];
    float Bs[2][32][40];
};

#define MMA_STAGE(BUF, AA0, AA1, AA2, AA3, BB0, BB1)                                     \
    {                                                                                    \
        float4 c0 = tf32c4(AA0), c1 = tf32c4(AA1), c2 = tf32c4(AA2), c3 = tf32c4(AA3);   \
        *(float4*)&S->As[BUF][am][ac] = c0;                                              \
        *(float4*)&S->As[BUF][am][ac + 4] = c1;                                          \
        *(float4*)&S->As[BUF][am + 32][ac] = c2;                                         \
        *(float4*)&S->As[BUF][am + 32][ac + 4] = c3;                                     \
        *(float4*)&S->Bs[BUF][bk][bc] = tf32c4(BB0);                                     \
        *(float4*)&S->Bs[BUF][bk][bc + 4] = tf32c4(BB1);                                 \
    }

#define MMA_COMPUTE(BUF)                                                                 \
    _Pragma("unroll") for (int ks = 0; ks < 4; ks++) {                                   \
        const int kb = ks * 8;                                                           \
        uint32_t a0 = __float_as_uint(S->As[BUF][w16 + g][kb + tig]);                    \
        uint32_t a1 = __float_as_uint(S->As[BUF][w16 + g + 8][kb + tig]);                \
        uint32_t a2 = __float_as_uint(S->As[BUF][w16 + g][kb + tig + 4]);                \
        uint32_t a3 = __float_as_uint(S->As[BUF][w16 + g + 8][kb + tig + 4]);            \
        _Pragma("unroll") for (int nb = 0; nb < 4; nb++) {                               \
            uint32_t b0 = __float_as_uint(S->Bs[BUF][kb + tig][nb * 8 + g]);             \
            uint32_t b1 = __float_as_uint(S->Bs[BUF][kb + tig + 4][nb * 8 + g]);         \
            mma_tf32(acc[nb], a0, a1, a2, a3, b0, b1);                                   \
        }                                                                                \
    }

__device__ __forceinline__ void gemm_mma(const float* A0, const float* A1, bool v0, bool v1,
                                         const float* Bb, int ldb, int k0, int nIter,
                                         MmaSmem* S, float (&acc)[4][4]) {
    const int t = threadIdx.x;
    const int am = t >> 2, ac = (t & 3) << 3;
    const int bk = t >> 2, bc = (t & 3) << 3;
    const int w16 = (t >> 5) << 4;
    const int g = (t & 31) >> 2, tig = t & 3;
    const float4 z4 = make_float4(0.f, 0.f, 0.f, 0.f);
    {
        float4 a0 = v0 ? ld4(A0 + k0) : z4, a1 = v0 ? ld4(A0 + k0 + 4) : z4;
        float4 a2 = v1 ? ld4(A1 + k0) : z4, a3 = v1 ? ld4(A1 + k0 + 4) : z4;
        float4 b0 = ld4(Bb + (long long)k0 * ldb);
        float4 b1 = ld4(Bb + (long long)k0 * ldb + 4);
        MMA_STAGE(0, a0, a1, a2, a3, b0, b1)
    }
    __syncthreads();
    int buf = 0;
    for (int it = 0; it < nIter; ++it) {
        float4 a0, a1, a2, a3, b0, b1;
        const bool pf = (it + 1) < nIter;
        if (pf) {
            const int kn = k0 + ((it + 1) << 5);
            a0 = v0 ? ld4(A0 + kn) : z4; a1 = v0 ? ld4(A0 + kn + 4) : z4;
            a2 = v1 ? ld4(A1 + kn) : z4; a3 = v1 ? ld4(A1 + kn + 4) : z4;
            b0 = ld4(Bb + (long long)kn * ldb);
            b1 = ld4(Bb + (long long)kn * ldb + 4);
        }
        MMA_COMPUTE(buf)
        if (pf) {
            const int nb2 = buf ^ 1;
            __syncthreads();
            MMA_STAGE(nb2, a0, a1, a2, a3, b0, b1)
            __syncthreads();
            buf = nb2;
        }
    }
}

// ---------------- split-K GEMM stage with counter-fused deterministic reduce ----------------
// EPI 0: out += sum   1: out = relu(sum+bias)   2: out += sum+bias   3: out = sum
// Z is a template parameter -> reduce loop fully unrolled (concurrent L2 loads).
template <int EPI, int Z>
__device__ __forceinline__ void gemm_splitk(const float* A, int lda, const float* B, int ldb,
                                            int n0B, float* part, float* out,
                                            const float* bias, int N, int ldOut, int m0,
                                            int n0, int k0, int kPerZ, int z,
                                            int tileId, char* sraw, int* s_last) {
    MmaSmem* S = (MmaSmem*)sraw;
    const int t = threadIdx.x;
    const int am = t >> 2, ac = (t & 3) << 3;
    const int bc = (t & 3) << 3;
    const int w16 = (t >> 5) << 4;
    const int g = (t & 31) >> 2, tig = t & 3;
    const bool v0 = (m0 + am) < 100, v1 = (m0 + am + 32) < 100;
    const float* A0 = A + (long long)(m0 + am) * lda + ac;
    const float* A1 = A + (long long)(m0 + am + 32) * lda + ac;
    const float* Bb = B + (long long)(t >> 2) * ldb + n0B + bc;
    float acc[4][4] = {};
    gemm_mma(A0, A1, v0, v1, Bb, ldb, k0, kPerZ >> 5, S, acc);

    float* pp = part + (long long)z * 100 * N;
    const int r0 = m0 + w16 + g, r1 = r0 + 8;
#pragma unroll
    for (int nb = 0; nb < 4; nb++) {
        const int col = n0 + nb * 8 + tig * 2;
        if (r0 < 100) *(float2*)(pp + (long long)r0 * N + col) = make_float2(acc[nb][0], acc[nb][1]);
        if (r1 < 100) *(float2*)(pp + (long long)r1 * N + col) = make_float2(acc[nb][2], acc[nb][3]);
    }
    __threadfence();
    __syncthreads();
    if (t == 0) {
        int old = atomicAdd(&g_cnt[tileId], 1);
        *s_last = (old == Z - 1) ? 1 : 0;
    }
    __syncthreads();
    if (*s_last) {
        __threadfence();
#pragma unroll
        for (int nb = 0; nb < 4; nb++) {
            const int col = n0 + nb * 8 + tig * 2;
#pragma unroll
            for (int half = 0; half < 2; half++) {
                const int m = half ? r1 : r0;
                if (m >= 100) continue;
                float2 vz[Z];
#pragma unroll
                for (int zz = 0; zz < Z; zz++)
                    vz[zz] = __ldcg((const float2*)(part + (long long)zz * 100 * N +
                                                    (long long)m * N + col));
                float2 s2 = make_float2(0.f, 0.f);
#pragma unroll
                for (int zz = 0; zz < Z; zz++) { s2.x += vz[zz].x; s2.y += vz[zz].y; }
                float* op = out + (long long)m * ldOut + col;
                if (EPI == 0) {
                    op[0] += s2.x; op[1] += s2.y;
                } else if (EPI == 1) {
                    float2 b2 = *(const float2*)(bias + col);
                    op[0] = fmaxf(s2.x + b2.x, 0.f);
                    op[1] = fmaxf(s2.y + b2.y, 0.f);
                } else if (EPI == 2) {
                    float2 b2 = *(const float2*)(bias + col);
                    op[0] += s2.x + b2.x;
                    op[1] += s2.y + b2.y;
                } else {
                    op[0] = s2.x; op[1] = s2.y;
                }
            }
        }
        __syncthreads();
        if (t == 0) g_cnt[tileId] = 0;
    }
}

// ---------------- attention unit: one (query n, head h) per 128-thread block ----------------
__device__ __forceinline__ void attn_unit(const float* __restrict__ z, float* __restrict__ O,
                                          int n, int h, char* sraw) {
    float* sq = (float*)sraw;    // 128
    float* sa = sq + 128;        // 104
    float* red = sa + 104;       // 4
    const int tid = threadIdx.x;
    sq[tid] = z[n * 2048 + h * 128 + tid];
    __syncthreads();
    float s = -1e30f;
    if (tid < 100) {
        const float* kr = z + tid * 2048 + 512 + h * 128;
        float a = 0.f;
#pragma unroll 8
        for (int i = 0; i < 128; i++) a += sq[i] * kr[i];
        s = a * 0.1f;
    }
    float v = s;
#pragma unroll
    for (int o2 = 16; o2; o2 >>= 1) v = fmaxf(v, __shfl_xor_sync(0xffffffffu, v, o2));
    if ((tid & 31) == 0) red[tid >> 5] = v;
    __syncthreads();
    float mx = fmaxf(fmaxf(red[0], red[1]), fmaxf(red[2], red[3]));
    float e = (tid < 100) ? expf(s - mx) : 0.f;
    float sv = e;
#pragma unroll
    for (int o2 = 16; o2; o2 >>= 1) sv += __shfl_xor_sync(0xffffffffu, sv, o2);
    __syncthreads();
    if ((tid & 31) == 0) red[tid >> 5] = sv;
    __syncthreads();
    float sum = red[0] + red[1] + red[2] + red[3];
    if (tid < 100) sa[tid] = e / sum;
    __syncthreads();
#pragma unroll
    for (int pass = 0; pass < 2; pass++) {
        const int c = tid + pass * 128;
        const float* vb = z + 1024 + h * 256 + c;
        float a0 = 0.f, a1 = 0.f, a2 = 0.f, a3 = 0.f;
        for (int m = 0; m < 100; m += 4) {
            a0 += sa[m] * vb[(long long)m * 2048];
            a1 += sa[m + 1] * vb[(long long)(m + 1) * 2048];
            a2 += sa[m + 2] * vb[(long long)(m + 2) * 2048];
            a3 += sa[m + 3] * vb[(long long)(m + 3) * 2048];
        }
        O[n * 1024 + h * 256 + c] = (a0 + a1) + (a2 + a3);
    }
    __syncthreads();
}

// ---------------- grid barrier (sense-forward, co-resident grid, bounded spin) ----------------
__device__ __forceinline__ void gbar(int& phase) {
    __syncthreads();
    if (threadIdx.x == 0) {
        __threadfence();
        int a = atomicAdd(&g_barCnt, 1);
        if (a == 511) {
            g_barCnt = 0;
            __threadfence();
            atomicExch(&g_barSense, phase + 1);
        } else {
            int it = 0;
            while (*((volatile int*)&g_barSense) <= phase && it < (1 << 25)) {
                __nanosleep(32);
                ++it;
            }
            __threadfence();
        }
    }
    __syncthreads();
    phase++;
}

// ---------------- persistent encoder: all 12 layers, one launch ----------------
__global__ __launch_bounds__(128, 4) void encoder_kernel(
    float* __restrict__ h, const float* __restrict__ Wq, const float* __restrict__ Wk,
    const float* __restrict__ Wv, const float* __restrict__ Wo,
    const float* __restrict__ W1, const float* __restrict__ b1,
    const float* __restrict__ W2, const float* __restrict__ b2) {
    __shared__ __align__(16) char sraw[sizeof(MmaSmem)];
    __shared__ int s_last;
    __shared__ int s_ph;
    const int b = blockIdx.x;
    if (threadIdx.x == 0) s_ph = *((volatile int*)&g_barSense);
    __syncthreads();
    int phase = s_ph;

    for (int l = 0; l < 12; l++) {
        const float* wq = Wq + (size_t)l * 262144;
        const float* wk = Wk + (size_t)l * 262144;
        const float* wv = Wv + (size_t)l * 524288;
        const float* wo = Wo + (size_t)l * 524288;
        const float* w1 = W1 + (size_t)l * 1048576;
        const float* bb1 = b1 + (size_t)l * 2048;
        const float* w2 = W2 + (size_t)l * 1048576;
        const float* bb2 = b2 + (size_t)l * 512;

        {  // stage 1: z = h @ [Wq|Wk|Wv]  (512 tiles = 64n x 2m x 4z, fold fused)
            const int zz = b & 3, mt = (b >> 2) & 1, nt = b >> 3;
            const int n0 = nt * 32, m0 = mt * 64, k0 = zz * 128;
            const float* Bp; int ldb, n0B;
            if (n0 < 512)       { Bp = wq + (n0 >> 7) * 65536; n0B = n0 & 127; ldb = 128; }
            else if (n0 < 1024) { int c = n0 - 512;  Bp = wk + (c >> 7) * 65536; n0B = c & 127; ldb = 128; }
            else                { int c = n0 - 1024; Bp = wv + (c >> 8) * 131072; n0B = c & 255; ldb = 256; }
            gemm_splitk<3, 4>(h, 512, Bp, ldb, n0B, g_zp, g_z, nullptr, 2048, 2048,
                              m0, n0, k0, 128, zz, nt * 2 + mt, sraw, &s_last);
        }
        gbar(phase);
        if (b < 400) attn_unit(g_z, g_o, b >> 2, b & 3, sraw);   // stage 2
        gbar(phase);
        {  // stage 3: h += O @ Wo  (512 tiles = 16n x 2m x 16z)
            const int zz = b & 15, mt = (b >> 4) & 1, nt = b >> 5;
            gemm_splitk<0, 16>(g_o, 1024, wo, 512, nt * 32, g_part, h, nullptr, 512, 512,
                               mt * 64, nt * 32, zz * 64, 64, zz, nt * 2 + mt, sraw, &s_last);
        }
        gbar(phase);
        {  // stage 4: t = relu(h @ W1 + b1)  (512 tiles = 64n x 2m x 4z)
            const int zz = b & 3, mt = (b >> 2) & 1, nt = b >> 3;
            gemm_splitk<1, 4>(h, 512, w1, 2048, nt * 32, g_zp, g_t, bb1, 2048, 2048,
                              mt * 64, nt * 32, zz * 128, 128, zz, nt * 2 + mt, sraw, &s_last);
        }
        gbar(phase);
        {  // stage 5: h += t @ W2 + b2  (512 tiles = 16n x 2m x 16z)
            const int zz = b & 15, mt = (b >> 4) & 1, nt = b >> 5;
            gemm_splitk<2, 16>(g_t, 2048, w2, 512, nt * 32, g_part, h, bb2, 512, 512,
                               mt * 64, nt * 32, zz * 128, 128, zz, nt * 2 + mt, sraw, &s_last);
        }
        gbar(phase);
    }
}

// ---------------- host launcher ----------------
extern "C" void kernel_launch(void* const* d_in, const int* in_sizes, int n_in,
                              void* d_out, int out_size) {
    const float* x = (const float*)d_in[0];
    const float* cw[10];
    const float* cb[10];
    for (int i = 0; i < 10; i++) {
        cw[i] = (const float*)d_in[1 + 2 * i];
        cb[i] = (const float*)d_in[2 + 2 * i];
    }
    const float* Wq = (const float*)d_in[21];
    const float* Wk = (const float*)d_in[22];
    const float* Wv = (const float*)d_in[23];
    const float* Wo = (const float*)d_in[24];
    const float* W1 = (const float*)d_in[25];
    const float* b1 = (const float*)d_in[26];
    const float* W2 = (const float*)d_in[27];
    const float* b2 = (const float*)d_in[28];
    float* h = (float*)d_out;

    float *bufA, *bufB;
    cudaGetSymbolAddress((void**)&bufA, g_bufA);
    cudaGetSymbolAddress((void**)&bufB, g_bufB);

    // ---- conv stack (grid.y widened for occupancy) ----
    conv1_kernel<<<100, 256>>>(x, cw[0], cb[0], bufA);
    conv_blk<8, 8, 16, 4, 18, 2, 4, true, 128><<<dim3(100, 4), 128>>>(bufA, cw[1], cb[1], bufB);
    conv_blk<16, 16, 32, 8, 16, 4, 2, false, 196><<<dim3(100, 4), 196>>>(bufB, cw[2], cb[2], bufA);
    conv_blk<32, 16, 32, 8, 14, 4, 2, true, 144><<<dim3(100, 4), 144>>>(bufA, cw[3], cb[3], bufB);
    conv_blk<32, 16, 64, 16, 12, 4, 2, true, 200><<<dim3(100, 4), 200>>>(bufB, cw[4], cb[4], bufA);
    conv_blk<64, 16, 64, 16, 10, 4, 2, true, 128><<<dim3(100, 4), 128>>>(bufA, cw[5], cb[5], bufB);
    conv_blk<64, 8, 128, 32, 8, 4, 2, true, 144><<<dim3(100, 4), 144>>>(bufB, cw[6], cb[6], bufA);
    conv_blk<128, 8, 128, 64, 6, 4, 2, true, 128><<<dim3(100, 2), 128>>>(bufA, cw[7], cb[7], bufB);
    conv_blk<128, 8, 256, 128, 4, 4, 1, true, 128><<<dim3(100, 2), 128>>>(bufB, cw[8], cb[8], bufA);
    gemmT_loc<<<dim3(16, 2), 128>>>(bufA, cw[9], cb[9], h);

    // ---- all 12 encoder layers in one persistent launch ----
    encoder_kernel<<<512, 128>>>(h, Wq, Wk, Wv, Wo, W1, b1, W2, b2);
}